// round 2
// baseline (speedup 1.0000x reference)
#include <cuda_runtime.h>
#include <cuda_bf16.h>
#include <math.h>

#define NMAX 50000
#define EMAX 1600000
#define DMODEL 256
#define NHEAD 8
#define HD 32

// ---------------- scratch (static device globals; no allocation) -------------
__device__ float g_xn  [(size_t)NMAX * DMODEL];
__device__ float g_q   [(size_t)NMAX * DMODEL];
__device__ float g_k   [(size_t)NMAX * DMODEL];
__device__ float g_v   [(size_t)NMAX * DMODEL];
__device__ float g_ep  [(size_t)EMAX * HD];
__device__ float g_sc  [(size_t)EMAX * NHEAD];   // scores, then exp(scores-max)
__device__ unsigned g_smax [(size_t)NMAX * NHEAD];
__device__ float g_ssum[(size_t)NMAX * NHEAD];
__device__ float g_agg [(size_t)NMAX * DMODEL];
__device__ float g_x1  [(size_t)NMAX * DMODEL];
__device__ float g_xn2 [(size_t)NMAX * DMODEL];
__device__ float g_ff  [(size_t)NMAX * 4 * DMODEL];

// ordered-uint encoding for float atomicMax
__device__ __forceinline__ unsigned fenc(float f) {
    unsigned u = __float_as_uint(f);
    return (u & 0x80000000u) ? ~u : (u | 0x80000000u);
}
__device__ __forceinline__ float fdec(unsigned u) {
    return (u & 0x80000000u) ? __uint_as_float(u & 0x7FFFFFFFu) : __uint_as_float(~u);
}

// ---------------- init: zero agg/ssum, smax = enc(-inf) ---------------------
__global__ __launch_bounds__(256) void init_kernel(int Nn) {
    int i = blockIdx.x * 256 + threadIdx.x;
    int nAgg = Nn * DMODEL;
    int n8 = Nn * NHEAD;
    if (i < nAgg) g_agg[i] = 0.f;
    if (i < n8) { g_smax[i] = 0x007FFFFFu; g_ssum[i] = 0.f; }
}

// ---------------- LayerNorm: one warp per node ------------------------------
__global__ __launch_bounds__(256) void ln_kernel(const float* __restrict__ x,
                                                 const float* __restrict__ g,
                                                 const float* __restrict__ b,
                                                 float* __restrict__ out, int Nn) {
    int warp = (blockIdx.x * 256 + threadIdx.x) >> 5;
    int lane = threadIdx.x & 31;
    if (warp >= Nn) return;
    const float4* xr = (const float4*)(x + (size_t)warp * DMODEL);
    float4 a = xr[lane];
    float4 c = xr[lane + 32];
    float s = a.x + a.y + a.z + a.w + c.x + c.y + c.z + c.w;
    float q = a.x*a.x + a.y*a.y + a.z*a.z + a.w*a.w
            + c.x*c.x + c.y*c.y + c.z*c.z + c.w*c.w;
    #pragma unroll
    for (int o = 16; o; o >>= 1) {
        s += __shfl_xor_sync(0xFFFFFFFFu, s, o);
        q += __shfl_xor_sync(0xFFFFFFFFu, q, o);
    }
    float mu = s * (1.f / 256.f);
    float var = q * (1.f / 256.f) - mu * mu;
    float inv = rsqrtf(var + 1e-5f);
    float4 g0 = ((const float4*)g)[lane], g1 = ((const float4*)g)[lane + 32];
    float4 b0 = ((const float4*)b)[lane], b1 = ((const float4*)b)[lane + 32];
    float4 o0, o1;
    o0.x = (a.x - mu) * inv * g0.x + b0.x;
    o0.y = (a.y - mu) * inv * g0.y + b0.y;
    o0.z = (a.z - mu) * inv * g0.z + b0.z;
    o0.w = (a.w - mu) * inv * g0.w + b0.w;
    o1.x = (c.x - mu) * inv * g1.x + b1.x;
    o1.y = (c.y - mu) * inv * g1.y + b1.y;
    o1.z = (c.z - mu) * inv * g1.z + b1.z;
    o1.w = (c.w - mu) * inv * g1.w + b1.w;
    float4* orow = (float4*)(out + (size_t)warp * DMODEL);
    orow[lane] = o0;
    orow[lane + 32] = o1;
}

// ---------------- generic GEMM: C = epi(A @ W^T + bias) ---------------------
// A[M,K], W[N,K] row-major. EPI: 0=bias, 1=bias+gelu, 2=R + scl*(.+bias)
#define BM 128
#define BN 64
#define BK 16

template <int EPI>
__global__ __launch_bounds__(256) void gemm_kernel(
    const float* __restrict__ A, const float* __restrict__ W,
    const float* __restrict__ bias, const float* __restrict__ R,
    const float* __restrict__ scl, float* __restrict__ C,
    int M, int N, int K) {
    __shared__ float As[BK][BM];
    __shared__ float Bs[BK][BN];
    int tid = threadIdx.x;
    int m0 = blockIdx.y * BM;
    int n0 = blockIdx.x * BN;

    int lr = tid >> 2;          // 0..63
    int lc = (tid & 3) << 2;    // 0,4,8,12

    int ty = tid >> 4;          // 0..15 -> rows ty*8..ty*8+7
    int tx = tid & 15;          // cols tx*4..tx*4+3

    float acc[8][4];
    #pragma unroll
    for (int i = 0; i < 8; i++)
        #pragma unroll
        for (int j = 0; j < 4; j++) acc[i][j] = 0.f;

    for (int k0 = 0; k0 < K; k0 += BK) {
        #pragma unroll
        for (int rr = 0; rr < 2; rr++) {
            int m = m0 + lr + rr * 64;
            float4 a = (m < M) ? *(const float4*)(A + (size_t)m * K + k0 + lc)
                               : make_float4(0.f, 0.f, 0.f, 0.f);
            As[lc + 0][lr + rr * 64] = a.x;
            As[lc + 1][lr + rr * 64] = a.y;
            As[lc + 2][lr + rr * 64] = a.z;
            As[lc + 3][lr + rr * 64] = a.w;
        }
        {
            int n = n0 + lr;
            float4 w = *(const float4*)(W + (size_t)n * K + k0 + lc);
            Bs[lc + 0][lr] = w.x;
            Bs[lc + 1][lr] = w.y;
            Bs[lc + 2][lr] = w.z;
            Bs[lc + 3][lr] = w.w;
        }
        __syncthreads();
        #pragma unroll
        for (int kk = 0; kk < BK; kk++) {
            float4 a0 = *(const float4*)&As[kk][ty * 8];
            float4 a1 = *(const float4*)&As[kk][ty * 8 + 4];
            float4 b0 = *(const float4*)&Bs[kk][tx * 4];
            float ar[8] = {a0.x, a0.y, a0.z, a0.w, a1.x, a1.y, a1.z, a1.w};
            float br[4] = {b0.x, b0.y, b0.z, b0.w};
            #pragma unroll
            for (int i = 0; i < 8; i++)
                #pragma unroll
                for (int j = 0; j < 4; j++) acc[i][j] += ar[i] * br[j];
        }
        __syncthreads();
    }

    float al = (EPI == 2) ? scl[0] : 0.f;
    #pragma unroll
    for (int i = 0; i < 8; i++) {
        int m = m0 + ty * 8 + i;
        if (m >= M) continue;
        #pragma unroll
        for (int j = 0; j < 4; j++) {
            int n = n0 + tx * 4 + j;
            float v = acc[i][j] + bias[n];
            if (EPI == 1) v = 0.5f * v * (1.f + erff(v * 0.70710678118654752f));
            if (EPI == 2) v = R[(size_t)m * N + n] + al * v;
            C[(size_t)m * N + n] = v;
        }
    }
}

// ---------------- edge projection: ep[E,32] = ef[E,32] @ We^T + be ----------
__global__ __launch_bounds__(256) void ep_kernel(const float* __restrict__ ef,
                                                 const float* __restrict__ We,
                                                 const float* __restrict__ be,
                                                 int E) {
    __shared__ float sWt[32 * 32];  // transposed: sWt[i*32+j] = We[j*32+i]
    __shared__ float sB[32];
    __shared__ float sEf[8][33];
    int tid = threadIdx.x;
    for (int t = tid; t < 1024; t += 256) {
        int j = t >> 5, i = t & 31;
        sWt[i * 32 + j] = We[t];
    }
    if (tid < 32) sB[tid] = be[tid];
    __syncthreads();
    int el = tid >> 5, j = tid & 31;
    for (int e0 = blockIdx.x * 8; e0 < E; e0 += gridDim.x * 8) {
        int e = e0 + el;
        __syncthreads();
        if (e < E) sEf[el][j] = ef[(size_t)e * 32 + j];
        __syncthreads();
        if (e < E) {
            float s = sB[j];
            #pragma unroll
            for (int i = 0; i < 32; i++) s += sEf[el][i] * sWt[i * 32 + j];
            g_ep[(size_t)e * 32 + j] = s;
        }
    }
}

// ---------------- scores: warp per edge; atomic segment-max ------------------
__global__ __launch_bounds__(256) void scores_kernel(const int* __restrict__ src,
                                                     const int* __restrict__ dst,
                                                     const float* __restrict__ ew,
                                                     int E) {
    int e = (blockIdx.x * 256 + threadIdx.x) >> 5;
    int lane = threadIdx.x & 31;
    if (e >= E) return;
    int s = src[e], d = dst[e];
    float epl = g_ep[(size_t)e * 32 + lane];
    float w = ew[e] * 0.17677669529663687f;  // 1/sqrt(32)
    const float* qrow = g_q + (size_t)d * DMODEL;
    const float* krow = g_k + (size_t)s * DMODEL;
    #pragma unroll
    for (int h = 0; h < NHEAD; h++) {
        float p = qrow[h * 32 + lane] * (krow[h * 32 + lane] + epl);
        #pragma unroll
        for (int o = 16; o; o >>= 1) p += __shfl_xor_sync(0xFFFFFFFFu, p, o);
        if (lane == 0) {
            float sc = p * w;
            g_sc[(size_t)e * NHEAD + h] = sc;
            atomicMax(&g_smax[(size_t)d * NHEAD + h], fenc(sc));
        }
    }
}

// ---------------- exp(scores - max) + segment-sum ---------------------------
__global__ __launch_bounds__(256) void expsum_kernel(const int* __restrict__ dst, int E) {
    int i = blockIdx.x * 256 + threadIdx.x;
    if (i >= E * NHEAD) return;
    int e = i >> 3, h = i & 7;
    int d = dst[e];
    float m = fdec(g_smax[(size_t)d * NHEAD + h]);
    float v = __expf(g_sc[i] - m);
    g_sc[i] = v;
    atomicAdd(&g_ssum[(size_t)d * NHEAD + h], v);
}

// ---------------- aggregate: warp per edge, scatter-add ---------------------
__global__ __launch_bounds__(256) void agg_kernel(const int* __restrict__ src,
                                                  const int* __restrict__ dst,
                                                  float* __restrict__ out_attn,
                                                  int E) {
    int e = (blockIdx.x * 256 + threadIdx.x) >> 5;
    int lane = threadIdx.x & 31;
    if (e >= E) return;
    int s = src[e], d = dst[e];
    float aw = 0.f;
    if (lane < NHEAD) {
        aw = g_sc[(size_t)e * NHEAD + lane] / g_ssum[(size_t)d * NHEAD + lane];
        out_attn[(size_t)e * NHEAD + lane] = aw;
    }
    const float* vrow = g_v + (size_t)s * DMODEL;
    float* arow = g_agg + (size_t)d * DMODEL;
    #pragma unroll
    for (int h = 0; h < NHEAD; h++) {
        float a = __shfl_sync(0xFFFFFFFFu, aw, h);
        atomicAdd(&arow[h * 32 + lane], a * vrow[h * 32 + lane]);
    }
}

// ---------------- host launcher ---------------------------------------------
static float* sym_addr(const void* symbol) {
    void* p = nullptr;
    cudaGetSymbolAddress(&p, symbol);
    return (float*)p;
}

extern "C" void kernel_launch(void* const* d_in, const int* in_sizes, int n_in,
                              void* d_out, int out_size) {
    const float* x  = (const float*)d_in[0];
    const int*   ei = (const int*)d_in[1];
    const float* ef = (const float*)d_in[2];
    const float* ew = (const float*)d_in[3];
    const float* Wq = (const float*)d_in[4];
    const float* bq = (const float*)d_in[5];
    const float* Wk = (const float*)d_in[6];
    const float* bk = (const float*)d_in[7];
    const float* Wv = (const float*)d_in[8];
    const float* bv = (const float*)d_in[9];
    const float* We = (const float*)d_in[10];
    const float* be = (const float*)d_in[11];
    const float* Wo = (const float*)d_in[12];
    const float* bo = (const float*)d_in[13];
    const float* W1 = (const float*)d_in[14];
    const float* b1 = (const float*)d_in[15];
    const float* W2 = (const float*)d_in[16];
    const float* b2 = (const float*)d_in[17];
    const float* g1 = (const float*)d_in[18];
    const float* be1 = (const float*)d_in[19];
    const float* g2 = (const float*)d_in[20];
    const float* be2 = (const float*)d_in[21];
    const float* alpha = (const float*)d_in[22];
    const float* beta  = (const float*)d_in[23];

    int Nn = in_sizes[0] / DMODEL;
    int E  = in_sizes[1] / 2;
    const int* src = ei;
    const int* dst = ei + E;

    float* out_x    = (float*)d_out;
    float* out_attn = out_x + (size_t)Nn * DMODEL;

    float* xn  = sym_addr(g_xn);
    float* q   = sym_addr(g_q);
    float* k   = sym_addr(g_k);
    float* v   = sym_addr(g_v);
    float* agg = sym_addr(g_agg);
    float* x1  = sym_addr(g_x1);
    float* xn2 = sym_addr(g_xn2);
    float* ff  = sym_addr(g_ff);

    // 1. init softmax/agg state
    {
        int tot = Nn * DMODEL;
        init_kernel<<<(tot + 255) / 256, 256>>>(Nn);
    }
    // 2. LN1
    {
        int blocks = (Nn * 32 + 255) / 256;
        ln_kernel<<<blocks, 256>>>(x, g1, be1, xn, Nn);
    }
    // 3. q, k, v projections
    {
        dim3 grid(DMODEL / BN, (Nn + BM - 1) / BM);
        gemm_kernel<0><<<grid, 256>>>(xn, Wq, bq, nullptr, nullptr, q, Nn, DMODEL, DMODEL);
        gemm_kernel<0><<<grid, 256>>>(xn, Wk, bk, nullptr, nullptr, k, Nn, DMODEL, DMODEL);
        gemm_kernel<0><<<grid, 256>>>(xn, Wv, bv, nullptr, nullptr, v, Nn, DMODEL, DMODEL);
    }
    // 4. edge projection
    ep_kernel<<<4096, 256>>>(ef, We, be, E);
    // 5. scores + segment max
    scores_kernel<<<(E * 32 + 255) / 256, 256>>>(src, dst, ew, E);
    // 6. exp + segment sum
    expsum_kernel<<<(E * NHEAD + 255) / 256, 256>>>(dst, E);
    // 7. aggregate + write attn weights
    agg_kernel<<<(E * 32 + 255) / 256, 256>>>(src, dst, out_attn, E);
    // 8. output projection + residual -> x1
    {
        dim3 grid(DMODEL / BN, (Nn + BM - 1) / BM);
        gemm_kernel<2><<<grid, 256>>>(agg, Wo, bo, x, alpha, x1, Nn, DMODEL, DMODEL);
    }
    // 9. LN2
    {
        int blocks = (Nn * 32 + 255) / 256;
        ln_kernel<<<blocks, 256>>>(x1, g2, be2, xn2, Nn);
    }
    // 10. FF1 + gelu
    {
        dim3 grid((4 * DMODEL) / BN, (Nn + BM - 1) / BM);
        gemm_kernel<1><<<grid, 256>>>(xn2, W1, b1, nullptr, nullptr, ff, Nn, 4 * DMODEL, DMODEL);
    }
    // 11. FF2 + residual -> out
    {
        dim3 grid(DMODEL / BN, (Nn + BM - 1) / BM);
        gemm_kernel<2><<<grid, 256>>>(ff, W2, b2, x1, beta, out_x, Nn, DMODEL, 4 * DMODEL);
    }
}

// round 3
// speedup vs baseline: 1.5784x; 1.5784x over previous
#include <cuda_runtime.h>
#include <cuda_bf16.h>
#include <math.h>

#define NMAX 50000
#define EMAX 1600000
#define DMODEL 256
#define NHEAD 8
#define HD 32

// ---------------- scratch (static device globals; no allocation) -------------
__device__ float g_xn  [(size_t)NMAX * DMODEL];
__device__ float g_q   [(size_t)NMAX * DMODEL];
__device__ float g_k   [(size_t)NMAX * DMODEL];
__device__ float g_v   [(size_t)NMAX * DMODEL];
__device__ float g_ep  [(size_t)EMAX * HD];
__device__ float g_sc  [(size_t)EMAX * NHEAD];   // scores, then exp(scores-max)
__device__ unsigned g_smax [(size_t)NMAX * NHEAD];
__device__ float g_ssum[(size_t)NMAX * NHEAD];
__device__ float g_agg [(size_t)NMAX * DMODEL];
__device__ float g_x1  [(size_t)NMAX * DMODEL];
__device__ float g_xn2 [(size_t)NMAX * DMODEL];
__device__ float g_ff  [(size_t)NMAX * 4 * DMODEL];

// ordered-uint encoding for float atomicMax
__device__ __forceinline__ unsigned fenc(float f) {
    unsigned u = __float_as_uint(f);
    return (u & 0x80000000u) ? ~u : (u | 0x80000000u);
}
__device__ __forceinline__ float fdec(unsigned u) {
    return (u & 0x80000000u) ? __uint_as_float(u & 0x7FFFFFFFu) : __uint_as_float(~u);
}

__device__ __forceinline__ unsigned f2tf32(float f) {
    unsigned r;
    asm("cvt.rna.tf32.f32 %0, %1;" : "=r"(r) : "f"(f));
    return r;
}

// ---------------- init: zero agg/ssum, smax = enc(-inf) ---------------------
__global__ __launch_bounds__(256) void init_kernel(int Nn) {
    int i = blockIdx.x * 256 + threadIdx.x;
    int nAgg = Nn * DMODEL;
    int n8 = Nn * NHEAD;
    if (i < nAgg) g_agg[i] = 0.f;
    if (i < n8) { g_smax[i] = 0x007FFFFFu; g_ssum[i] = 0.f; }
}

// ---------------- LayerNorm: one warp per node ------------------------------
__global__ __launch_bounds__(256) void ln_kernel(const float* __restrict__ x,
                                                 const float* __restrict__ g,
                                                 const float* __restrict__ b,
                                                 float* __restrict__ out, int Nn) {
    int warp = (blockIdx.x * 256 + threadIdx.x) >> 5;
    int lane = threadIdx.x & 31;
    if (warp >= Nn) return;
    const float4* xr = (const float4*)(x + (size_t)warp * DMODEL);
    float4 a = xr[lane];
    float4 c = xr[lane + 32];
    float s = a.x + a.y + a.z + a.w + c.x + c.y + c.z + c.w;
    float q = a.x*a.x + a.y*a.y + a.z*a.z + a.w*a.w
            + c.x*c.x + c.y*c.y + c.z*c.z + c.w*c.w;
    #pragma unroll
    for (int o = 16; o; o >>= 1) {
        s += __shfl_xor_sync(0xFFFFFFFFu, s, o);
        q += __shfl_xor_sync(0xFFFFFFFFu, q, o);
    }
    float mu = s * (1.f / 256.f);
    float var = q * (1.f / 256.f) - mu * mu;
    float inv = rsqrtf(var + 1e-5f);
    float4 g0 = ((const float4*)g)[lane], g1 = ((const float4*)g)[lane + 32];
    float4 b0 = ((const float4*)b)[lane], b1 = ((const float4*)b)[lane + 32];
    float4 o0, o1;
    o0.x = (a.x - mu) * inv * g0.x + b0.x;
    o0.y = (a.y - mu) * inv * g0.y + b0.y;
    o0.z = (a.z - mu) * inv * g0.z + b0.z;
    o0.w = (a.w - mu) * inv * g0.w + b0.w;
    o1.x = (c.x - mu) * inv * g1.x + b1.x;
    o1.y = (c.y - mu) * inv * g1.y + b1.y;
    o1.z = (c.z - mu) * inv * g1.z + b1.z;
    o1.w = (c.w - mu) * inv * g1.w + b1.w;
    float4* orow = (float4*)(out + (size_t)warp * DMODEL);
    orow[lane] = o0;
    orow[lane + 32] = o1;
}

// ---------------- tf32 tensor-core GEMM: C = epi(A @ W^T + bias) ------------
// A[M,K], W[N,K] row-major. EPI: 0=bias, 1=bias+gelu, 2=R + scl*(.+bias)
// CTA tile 128x64, BK=32. 8 warps: wm=warp&3 (32 rows each), wn=warp>>2 (32 cols each).
// mma.sync.m16n8k8 tf32. Smem stride 36 words => conflict-free frag loads.
#define TBM 128
#define TBN 64
#define TBK 32
#define SSTR 36

__device__ __forceinline__ void mma_tf32(float c[4], const unsigned a[4], const unsigned b[2]) {
    asm volatile(
        "mma.sync.aligned.m16n8k8.row.col.f32.tf32.tf32.f32 "
        "{%0,%1,%2,%3},{%4,%5,%6,%7},{%8,%9},{%0,%1,%2,%3};\n"
        : "+f"(c[0]), "+f"(c[1]), "+f"(c[2]), "+f"(c[3])
        : "r"(a[0]), "r"(a[1]), "r"(a[2]), "r"(a[3]), "r"(b[0]), "r"(b[1]));
}

template <int EPI>
__global__ __launch_bounds__(256) void gemm_tc(
    const float* __restrict__ A, const float* __restrict__ W,
    const float* __restrict__ bias, const float* __restrict__ R,
    const float* __restrict__ scl, float* __restrict__ C,
    int M, int N, int K) {
    __shared__ unsigned As[TBM * SSTR];
    __shared__ unsigned Bs[TBN * SSTR];
    const int tid = threadIdx.x;
    const int m0 = blockIdx.y * TBM;
    const int n0 = blockIdx.x * TBN;
    const int warp = tid >> 5, lane = tid & 31;
    const int wm = warp & 3, wn = warp >> 2;   // wm*32 rows, wn*32 cols
    const int g = lane >> 2, t = lane & 3;

    float acc[2][4][4];
    #pragma unroll
    for (int mi = 0; mi < 2; mi++)
        #pragma unroll
        for (int ni = 0; ni < 4; ni++)
            #pragma unroll
            for (int j = 0; j < 4; j++) acc[mi][ni][j] = 0.f;

    float4 pa[4], pb[2];

    // global load of one k-chunk into regs
    auto loadG = [&](int k0) {
        #pragma unroll
        for (int i = 0; i < 4; i++) {
            int id = tid + i * 256;
            int r = id >> 3, kk = (id & 7) * 4;
            int m = m0 + r;
            pa[i] = (m < M) ? *(const float4*)(A + (size_t)m * K + k0 + kk)
                            : make_float4(0.f, 0.f, 0.f, 0.f);
        }
        #pragma unroll
        for (int i = 0; i < 2; i++) {
            int id = tid + i * 256;
            int r = id >> 3, kk = (id & 7) * 4;
            pb[i] = *(const float4*)(W + (size_t)(n0 + r) * K + k0 + kk);
        }
    };
    auto sts = [&]() {
        #pragma unroll
        for (int i = 0; i < 4; i++) {
            int id = tid + i * 256;
            int r = id >> 3, kk = (id & 7) * 4;
            unsigned* p = &As[r * SSTR + kk];
            p[0] = f2tf32(pa[i].x); p[1] = f2tf32(pa[i].y);
            p[2] = f2tf32(pa[i].z); p[3] = f2tf32(pa[i].w);
        }
        #pragma unroll
        for (int i = 0; i < 2; i++) {
            int id = tid + i * 256;
            int r = id >> 3, kk = (id & 7) * 4;
            unsigned* p = &Bs[r * SSTR + kk];
            p[0] = f2tf32(pb[i].x); p[1] = f2tf32(pb[i].y);
            p[2] = f2tf32(pb[i].z); p[3] = f2tf32(pb[i].w);
        }
    };
    auto compute = [&]() {
        #pragma unroll
        for (int ks = 0; ks < 4; ks++) {
            int k = ks * 8;
            unsigned af[2][4], bf[4][2];
            #pragma unroll
            for (int mi = 0; mi < 2; mi++) {
                int r = wm * 32 + mi * 16;
                af[mi][0] = As[(r + g) * SSTR + k + t];
                af[mi][1] = As[(r + g + 8) * SSTR + k + t];
                af[mi][2] = As[(r + g) * SSTR + k + t + 4];
                af[mi][3] = As[(r + g + 8) * SSTR + k + t + 4];
            }
            #pragma unroll
            for (int ni = 0; ni < 4; ni++) {
                int c = wn * 32 + ni * 8 + g;
                bf[ni][0] = Bs[c * SSTR + k + t];
                bf[ni][1] = Bs[c * SSTR + k + t + 4];
            }
            #pragma unroll
            for (int mi = 0; mi < 2; mi++)
                #pragma unroll
                for (int ni = 0; ni < 4; ni++)
                    mma_tf32(acc[mi][ni], af[mi], bf[ni]);
        }
    };

    loadG(0);
    sts();
    __syncthreads();
    for (int k0 = TBK; k0 < K; k0 += TBK) {
        loadG(k0);          // global loads overlap compute below
        compute();
        __syncthreads();
        sts();
        __syncthreads();
    }
    compute();

    // epilogue: c0=(g,2t) c1=(g,2t+1) c2=(g+8,2t) c3=(g+8,2t+1)
    float al = (EPI == 2) ? scl[0] : 0.f;
    #pragma unroll
    for (int mi = 0; mi < 2; mi++) {
        #pragma unroll
        for (int ni = 0; ni < 4; ni++) {
            int col = n0 + wn * 32 + ni * 8 + 2 * t;
            float bx = bias[col], by = bias[col + 1];
            #pragma unroll
            for (int h = 0; h < 2; h++) {
                int row = m0 + wm * 32 + mi * 16 + g + h * 8;
                if (row >= M) continue;
                float v0 = acc[mi][ni][h * 2 + 0] + bx;
                float v1 = acc[mi][ni][h * 2 + 1] + by;
                if (EPI == 1) {
                    v0 = 0.5f * v0 * (1.f + erff(v0 * 0.70710678118654752f));
                    v1 = 0.5f * v1 * (1.f + erff(v1 * 0.70710678118654752f));
                }
                if (EPI == 2) {
                    const float* rr = R + (size_t)row * N + col;
                    v0 = rr[0] + al * v0;
                    v1 = rr[1] + al * v1;
                }
                *(float2*)(C + (size_t)row * N + col) = make_float2(v0, v1);
            }
        }
    }
}

// ---------------- edge projection: ep[E,32] = ef[E,32] @ We^T + be ----------
__global__ __launch_bounds__(256) void ep_kernel(const float* __restrict__ ef,
                                                 const float* __restrict__ We,
                                                 const float* __restrict__ be,
                                                 int E) {
    __shared__ float sWt[32 * 32];  // transposed: sWt[i*32+j] = We[j*32+i]
    __shared__ float sB[32];
    __shared__ float sEf[8][33];
    int tid = threadIdx.x;
    for (int t = tid; t < 1024; t += 256) {
        int j = t >> 5, i = t & 31;
        sWt[i * 32 + j] = We[t];
    }
    if (tid < 32) sB[tid] = be[tid];
    __syncthreads();
    int el = tid >> 5, j = tid & 31;
    for (int e0 = blockIdx.x * 8; e0 < E; e0 += gridDim.x * 8) {
        int e = e0 + el;
        __syncthreads();
        if (e < E) sEf[el][j] = ef[(size_t)e * 32 + j];
        __syncthreads();
        if (e < E) {
            float s = sB[j];
            #pragma unroll
            for (int i = 0; i < 32; i++) s += sEf[el][i] * sWt[i * 32 + j];
            g_ep[(size_t)e * 32 + j] = s;
        }
    }
}

// ---------------- scores: warp per edge; lane = (head, quarter) --------------
__global__ __launch_bounds__(256) void scores_kernel(const int* __restrict__ src,
                                                     const int* __restrict__ dst,
                                                     const float* __restrict__ ew,
                                                     int E) {
    int e = (blockIdx.x * 256 + threadIdx.x) >> 5;
    int lane = threadIdx.x & 31;
    if (e >= E) return;
    int s = src[e], d = dst[e];
    int h = lane >> 2, part = lane & 3;
    const float4* q4 = (const float4*)(g_q + (size_t)d * DMODEL + h * 32 + part * 8);
    const float4* k4 = (const float4*)(g_k + (size_t)s * DMODEL + h * 32 + part * 8);
    const float4* e4 = (const float4*)(g_ep + (size_t)e * 32 + part * 8);
    float4 qa = q4[0], qb = q4[1];
    float4 ka = k4[0], kb = k4[1];
    float4 ea = e4[0], eb = e4[1];
    float p = qa.x * (ka.x + ea.x) + qa.y * (ka.y + ea.y)
            + qa.z * (ka.z + ea.z) + qa.w * (ka.w + ea.w)
            + qb.x * (kb.x + eb.x) + qb.y * (kb.y + eb.y)
            + qb.z * (kb.z + eb.z) + qb.w * (kb.w + eb.w);
    p += __shfl_xor_sync(0xFFFFFFFFu, p, 1);
    p += __shfl_xor_sync(0xFFFFFFFFu, p, 2);
    if (part == 0) {
        float sc = p * ew[e] * 0.17677669529663687f;  // 1/sqrt(32)
        g_sc[(size_t)e * NHEAD + h] = sc;
        atomicMax(&g_smax[(size_t)d * NHEAD + h], fenc(sc));
    }
}

// ---------------- exp(scores - max) + segment-sum ---------------------------
__global__ __launch_bounds__(256) void expsum_kernel(const int* __restrict__ dst, int E) {
    int i = blockIdx.x * 256 + threadIdx.x;
    if (i >= E * NHEAD) return;
    int e = i >> 3, h = i & 7;
    int d = dst[e];
    float m = fdec(g_smax[(size_t)d * NHEAD + h]);
    float v = __expf(g_sc[i] - m);
    g_sc[i] = v;
    atomicAdd(&g_ssum[(size_t)d * NHEAD + h], v);
}

// ---------------- aggregate: warp per edge, scatter-add ---------------------
__global__ __launch_bounds__(256) void agg_kernel(const int* __restrict__ src,
                                                  const int* __restrict__ dst,
                                                  float* __restrict__ out_attn,
                                                  int E) {
    int e = (blockIdx.x * 256 + threadIdx.x) >> 5;
    int lane = threadIdx.x & 31;
    if (e >= E) return;
    int s = src[e], d = dst[e];
    float aw = 0.f;
    if (lane < NHEAD) {
        aw = g_sc[(size_t)e * NHEAD + lane] / g_ssum[(size_t)d * NHEAD + lane];
        out_attn[(size_t)e * NHEAD + lane] = aw;
    }
    const float* vrow = g_v + (size_t)s * DMODEL;
    float* arow = g_agg + (size_t)d * DMODEL;
    #pragma unroll
    for (int h = 0; h < NHEAD; h++) {
        float a = __shfl_sync(0xFFFFFFFFu, aw, h);
        atomicAdd(&arow[h * 32 + lane], a * vrow[h * 32 + lane]);
    }
}

// ---------------- host launcher ---------------------------------------------
static float* sym_addr(const void* symbol) {
    void* p = nullptr;
    cudaGetSymbolAddress(&p, symbol);
    return (float*)p;
}

extern "C" void kernel_launch(void* const* d_in, const int* in_sizes, int n_in,
                              void* d_out, int out_size) {
    const float* x  = (const float*)d_in[0];
    const int*   ei = (const int*)d_in[1];
    const float* ef = (const float*)d_in[2];
    const float* ew = (const float*)d_in[3];
    const float* Wq = (const float*)d_in[4];
    const float* bq = (const float*)d_in[5];
    const float* Wk = (const float*)d_in[6];
    const float* bk = (const float*)d_in[7];
    const float* Wv = (const float*)d_in[8];
    const float* bv = (const float*)d_in[9];
    const float* We = (const float*)d_in[10];
    const float* be = (const float*)d_in[11];
    const float* Wo = (const float*)d_in[12];
    const float* bo = (const float*)d_in[13];
    const float* W1 = (const float*)d_in[14];
    const float* b1 = (const float*)d_in[15];
    const float* W2 = (const float*)d_in[16];
    const float* b2 = (const float*)d_in[17];
    const float* g1 = (const float*)d_in[18];
    const float* be1 = (const float*)d_in[19];
    const float* g2 = (const float*)d_in[20];
    const float* be2 = (const float*)d_in[21];
    const float* alpha = (const float*)d_in[22];
    const float* beta  = (const float*)d_in[23];

    int Nn = in_sizes[0] / DMODEL;
    int E  = in_sizes[1] / 2;
    const int* src = ei;
    const int* dst = ei + E;

    float* out_x    = (float*)d_out;
    float* out_attn = out_x + (size_t)Nn * DMODEL;

    float* xn  = sym_addr(g_xn);
    float* q   = sym_addr(g_q);
    float* k   = sym_addr(g_k);
    float* v   = sym_addr(g_v);
    float* agg = sym_addr(g_agg);
    float* x1  = sym_addr(g_x1);
    float* xn2 = sym_addr(g_xn2);
    float* ff  = sym_addr(g_ff);

    int gy = (Nn + TBM - 1) / TBM;

    // 1. init softmax/agg state
    {
        int tot = Nn * DMODEL;
        init_kernel<<<(tot + 255) / 256, 256>>>(Nn);
    }
    // 2. LN1
    {
        int blocks = (Nn * 32 + 255) / 256;
        ln_kernel<<<blocks, 256>>>(x, g1, be1, xn, Nn);
    }
    // 3. q, k, v projections (tf32 TC)
    {
        dim3 grid(DMODEL / TBN, gy);
        gemm_tc<0><<<grid, 256>>>(xn, Wq, bq, nullptr, nullptr, q, Nn, DMODEL, DMODEL);
        gemm_tc<0><<<grid, 256>>>(xn, Wk, bk, nullptr, nullptr, k, Nn, DMODEL, DMODEL);
        gemm_tc<0><<<grid, 256>>>(xn, Wv, bv, nullptr, nullptr, v, Nn, DMODEL, DMODEL);
    }
    // 4. edge projection
    ep_kernel<<<4096, 256>>>(ef, We, be, E);
    // 5. scores + segment max
    scores_kernel<<<(E * 32 + 255) / 256, 256>>>(src, dst, ew, E);
    // 6. exp + segment sum
    expsum_kernel<<<(E * NHEAD + 255) / 256, 256>>>(dst, E);
    // 7. aggregate + write attn weights
    agg_kernel<<<(E * 32 + 255) / 256, 256>>>(src, dst, out_attn, E);
    // 8. output projection + residual -> x1
    {
        dim3 grid(DMODEL / TBN, gy);
        gemm_tc<2><<<grid, 256>>>(agg, Wo, bo, x, alpha, x1, Nn, DMODEL, DMODEL);
    }
    // 9. LN2
    {
        int blocks = (Nn * 32 + 255) / 256;
        ln_kernel<<<blocks, 256>>>(x1, g2, be2, xn2, Nn);
    }
    // 10. FF1 + gelu
    {
        dim3 grid((4 * DMODEL) / TBN, gy);
        gemm_tc<1><<<grid, 256>>>(xn2, W1, b1, nullptr, nullptr, ff, Nn, 4 * DMODEL, DMODEL);
    }
    // 11. FF2 + residual -> out
    {
        dim3 grid(DMODEL / TBN, gy);
        gemm_tc<2><<<grid, 256>>>(ff, W2, b2, x1, beta, out_x, Nn, DMODEL, 4 * DMODEL);
    }
}

// round 4
// speedup vs baseline: 2.1167x; 1.3410x over previous
#include <cuda_runtime.h>
#include <cuda_bf16.h>
#include <math.h>

#define NMAX 50000
#define EMAX 1600000
#define DMODEL 256
#define NHEAD 8
#define HD 32

// ---------------- scratch (static device globals; no allocation) -------------
__device__ float g_xn  [(size_t)NMAX * DMODEL];
__device__ float g_q   [(size_t)NMAX * DMODEL];
__device__ float g_k   [(size_t)NMAX * DMODEL];
__device__ float g_v   [(size_t)NMAX * DMODEL];
__device__ float g_ep  [(size_t)EMAX * HD];
__device__ float g_sc  [(size_t)EMAX * NHEAD];   // sorted-slot scores -> exp weights
__device__ float g_agg [(size_t)NMAX * DMODEL];
__device__ float g_x1  [(size_t)NMAX * DMODEL];
__device__ float g_xn2 [(size_t)NMAX * DMODEL];
__device__ float g_ff  [(size_t)NMAX * 4 * DMODEL];
// CSR build
__device__ int g_cnt   [NMAX];
__device__ int g_cur   [NMAX];
__device__ int g_rowptr[NMAX + 1];
__device__ int g_perm  [EMAX];
__device__ int g_src_s [EMAX];
__device__ int g_dst_s [EMAX];

__device__ __forceinline__ unsigned smem_u32(const void* p) {
    return (unsigned)__cvta_generic_to_shared(p);
}
__device__ __forceinline__ void cp_async16(unsigned daddr, const void* gptr, int szbytes) {
    asm volatile("cp.async.cg.shared.global [%0], [%1], 16, %2;\n"
                 :: "r"(daddr), "l"(gptr), "r"(szbytes));
}

// ---------------- init: zero CSR counters -----------------------------------
__global__ __launch_bounds__(256) void init_kernel(int Nn) {
    int i = blockIdx.x * 256 + threadIdx.x;
    if (i < Nn) { g_cnt[i] = 0; g_cur[i] = 0; }
}

// ---------------- LayerNorm: one warp per node ------------------------------
__global__ __launch_bounds__(256) void ln_kernel(const float* __restrict__ x,
                                                 const float* __restrict__ g,
                                                 const float* __restrict__ b,
                                                 float* __restrict__ out, int Nn) {
    int warp = (blockIdx.x * 256 + threadIdx.x) >> 5;
    int lane = threadIdx.x & 31;
    if (warp >= Nn) return;
    const float4* xr = (const float4*)(x + (size_t)warp * DMODEL);
    float4 a = xr[lane];
    float4 c = xr[lane + 32];
    float s = a.x + a.y + a.z + a.w + c.x + c.y + c.z + c.w;
    float q = a.x*a.x + a.y*a.y + a.z*a.z + a.w*a.w
            + c.x*c.x + c.y*c.y + c.z*c.z + c.w*c.w;
    #pragma unroll
    for (int o = 16; o; o >>= 1) {
        s += __shfl_xor_sync(0xFFFFFFFFu, s, o);
        q += __shfl_xor_sync(0xFFFFFFFFu, q, o);
    }
    float mu = s * (1.f / 256.f);
    float var = q * (1.f / 256.f) - mu * mu;
    float inv = rsqrtf(var + 1e-5f);
    float4 g0 = ((const float4*)g)[lane], g1 = ((const float4*)g)[lane + 32];
    float4 b0 = ((const float4*)b)[lane], b1 = ((const float4*)b)[lane + 32];
    float4 o0, o1;
    o0.x = (a.x - mu) * inv * g0.x + b0.x;
    o0.y = (a.y - mu) * inv * g0.y + b0.y;
    o0.z = (a.z - mu) * inv * g0.z + b0.z;
    o0.w = (a.w - mu) * inv * g0.w + b0.w;
    o1.x = (c.x - mu) * inv * g1.x + b1.x;
    o1.y = (c.y - mu) * inv * g1.y + b1.y;
    o1.z = (c.z - mu) * inv * g1.z + b1.z;
    o1.w = (c.w - mu) * inv * g1.w + b1.w;
    float4* orow = (float4*)(out + (size_t)warp * DMODEL);
    orow[lane] = o0;
    orow[lane + 32] = o1;
}

// ---------------- tf32 TC GEMM: C = epi(A @ W^T + bias) ---------------------
// CTA tile 128x128, BK=32, cp.async double buffer. 8 warps, warp tile 32x64.
#define TBM 128
#define TBN 128
#define TBK 32
#define SSTR 36
#define SMEM_WORDS (2 * (TBM + TBN) * SSTR)
#define SMEM_BYTES (SMEM_WORDS * 4)

__device__ __forceinline__ void mma_tf32(float c[4], const unsigned a[4], const unsigned b[2]) {
    asm volatile(
        "mma.sync.aligned.m16n8k8.row.col.f32.tf32.tf32.f32 "
        "{%0,%1,%2,%3},{%4,%5,%6,%7},{%8,%9},{%0,%1,%2,%3};\n"
        : "+f"(c[0]), "+f"(c[1]), "+f"(c[2]), "+f"(c[3])
        : "r"(a[0]), "r"(a[1]), "r"(a[2]), "r"(a[3]), "r"(b[0]), "r"(b[1]));
}

template <int EPI>
__global__ __launch_bounds__(256) void gemm_tc(
    const float* __restrict__ A, const float* __restrict__ W,
    const float* __restrict__ bias, const float* __restrict__ R,
    const float* __restrict__ scl, float* __restrict__ C,
    int M, int N, int K) {
    extern __shared__ unsigned smem[];
    unsigned* As = smem;                       // [2][TBM*SSTR]
    unsigned* Bs = smem + 2 * TBM * SSTR;      // [2][TBN*SSTR]
    const unsigned sAb = smem_u32(As);
    const unsigned sBb = smem_u32(Bs);
    const int tid = threadIdx.x;
    const int m0 = blockIdx.y * TBM;
    const int n0 = blockIdx.x * TBN;
    const int warp = tid >> 5, lane = tid & 31;
    const int wm = warp & 3, wn = warp >> 2;   // 32 rows, 64 cols per warp
    const int g = lane >> 2, t = lane & 3;

    float acc[2][8][4];
    #pragma unroll
    for (int mi = 0; mi < 2; mi++)
        #pragma unroll
        for (int ni = 0; ni < 8; ni++)
            #pragma unroll
            for (int j = 0; j < 4; j++) acc[mi][ni][j] = 0.f;

    auto stage = [&](int buf, int k0) {
        #pragma unroll
        for (int i = 0; i < 4; i++) {
            int ch = tid + i * 256;
            int r = ch >> 3, c4 = (ch & 7) * 4;
            int m = m0 + r;
            int ok = (m < M);
            const float* gp = A + (size_t)(ok ? m : 0) * K + k0 + c4;
            cp_async16(sAb + (unsigned)(buf * TBM * SSTR + r * SSTR + c4) * 4, gp, ok ? 16 : 0);
        }
        #pragma unroll
        for (int i = 0; i < 4; i++) {
            int ch = tid + i * 256;
            int r = ch >> 3, c4 = (ch & 7) * 4;
            const float* gp = W + (size_t)(n0 + r) * K + k0 + c4;
            cp_async16(sBb + (unsigned)(buf * TBN * SSTR + r * SSTR + c4) * 4, gp, 16);
        }
        asm volatile("cp.async.commit_group;\n");
    };

    auto compute = [&](int buf) {
        const unsigned* Ab = As + buf * TBM * SSTR;
        const unsigned* Bb = Bs + buf * TBN * SSTR;
        #pragma unroll
        for (int ks = 0; ks < 4; ks++) {
            int k = ks * 8;
            unsigned af[2][4], bf[8][2];
            #pragma unroll
            for (int mi = 0; mi < 2; mi++) {
                int r = wm * 32 + mi * 16;
                af[mi][0] = Ab[(r + g) * SSTR + k + t];
                af[mi][1] = Ab[(r + g + 8) * SSTR + k + t];
                af[mi][2] = Ab[(r + g) * SSTR + k + t + 4];
                af[mi][3] = Ab[(r + g + 8) * SSTR + k + t + 4];
            }
            #pragma unroll
            for (int ni = 0; ni < 8; ni++) {
                int c = wn * 64 + ni * 8 + g;
                bf[ni][0] = Bb[c * SSTR + k + t];
                bf[ni][1] = Bb[c * SSTR + k + t + 4];
            }
            #pragma unroll
            for (int mi = 0; mi < 2; mi++)
                #pragma unroll
                for (int ni = 0; ni < 8; ni++)
                    mma_tf32(acc[mi][ni], af[mi], bf[ni]);
        }
    };

    const int nk = K / TBK;
    stage(0, 0);
    int buf = 0;
    for (int kt = 0; kt < nk; kt++) {
        if (kt + 1 < nk) {
            stage(buf ^ 1, (kt + 1) * TBK);
            asm volatile("cp.async.wait_group 1;\n");
        } else {
            asm volatile("cp.async.wait_group 0;\n");
        }
        __syncthreads();
        compute(buf);
        __syncthreads();
        buf ^= 1;
    }

    // epilogue: c0=(g,2t) c1=(g,2t+1) c2=(g+8,2t) c3=(g+8,2t+1)
    float al = (EPI == 2) ? scl[0] : 0.f;
    #pragma unroll
    for (int mi = 0; mi < 2; mi++) {
        #pragma unroll
        for (int ni = 0; ni < 8; ni++) {
            int col = n0 + wn * 64 + ni * 8 + 2 * t;
            float bx = bias[col], by = bias[col + 1];
            #pragma unroll
            for (int h = 0; h < 2; h++) {
                int row = m0 + wm * 32 + mi * 16 + g + h * 8;
                if (row >= M) continue;
                float v0 = acc[mi][ni][h * 2 + 0] + bx;
                float v1 = acc[mi][ni][h * 2 + 1] + by;
                if (EPI == 1) {
                    v0 = 0.5f * v0 * (1.f + erff(v0 * 0.70710678118654752f));
                    v1 = 0.5f * v1 * (1.f + erff(v1 * 0.70710678118654752f));
                }
                if (EPI == 2) {
                    const float* rr = R + (size_t)row * N + col;
                    v0 = rr[0] + al * v0;
                    v1 = rr[1] + al * v1;
                }
                *(float2*)(C + (size_t)row * N + col) = make_float2(v0, v1);
            }
        }
    }
}

// ---------------- edge projection: ep[E,32] = ef[E,32] @ We^T + be ----------
__global__ __launch_bounds__(256) void ep_kernel(const float* __restrict__ ef,
                                                 const float* __restrict__ We,
                                                 const float* __restrict__ be,
                                                 int E) {
    __shared__ float sWt[32 * 32];
    __shared__ float sB[32];
    __shared__ float sEf[8][33];
    int tid = threadIdx.x;
    for (int t = tid; t < 1024; t += 256) {
        int j = t >> 5, i = t & 31;
        sWt[i * 32 + j] = We[t];
    }
    if (tid < 32) sB[tid] = be[tid];
    __syncthreads();
    int el = tid >> 5, j = tid & 31;
    for (int e0 = blockIdx.x * 8; e0 < E; e0 += gridDim.x * 8) {
        int e = e0 + el;
        __syncthreads();
        if (e < E) sEf[el][j] = ef[(size_t)e * 32 + j];
        __syncthreads();
        if (e < E) {
            float s = sB[j];
            #pragma unroll
            for (int i = 0; i < 32; i++) s += sEf[el][i] * sWt[i * 32 + j];
            g_ep[(size_t)e * 32 + j] = s;
        }
    }
}

// ---------------- CSR build --------------------------------------------------
__global__ __launch_bounds__(256) void hist_kernel(const int* __restrict__ dst, int E) {
    int i = blockIdx.x * 256 + threadIdx.x;
    if (i < E) atomicAdd(&g_cnt[dst[i]], 1);
}

__global__ __launch_bounds__(1024) void scan_kernel(int Nn, int E) {
    const int tid = threadIdx.x;
    const int lane = tid & 31, wid = tid >> 5;
    __shared__ int warp_sums[32];
    __shared__ int carry;
    if (tid == 0) carry = 0;
    __syncthreads();
    for (int base = 0; base < Nn; base += 1024) {
        int i = base + tid;
        int v = (i < Nn) ? g_cnt[i] : 0;
        int x = v;
        #pragma unroll
        for (int o = 1; o < 32; o <<= 1) {
            int y = __shfl_up_sync(0xFFFFFFFFu, x, o);
            if (lane >= o) x += y;
        }
        if (lane == 31) warp_sums[wid] = x;
        __syncthreads();
        if (wid == 0) {
            int s = warp_sums[lane];
            #pragma unroll
            for (int o = 1; o < 32; o <<= 1) {
                int y = __shfl_up_sync(0xFFFFFFFFu, s, o);
                if (lane >= o) s += y;
            }
            warp_sums[lane] = s;
        }
        __syncthreads();
        int offset = carry + (wid ? warp_sums[wid - 1] : 0);
        if (i < Nn) g_rowptr[i] = offset + x - v;
        int blocktotal = warp_sums[31];
        __syncthreads();
        if (tid == 0) carry += blocktotal;
        __syncthreads();
    }
    if (tid == 0) g_rowptr[Nn] = E;
}

__global__ __launch_bounds__(256) void scatter_kernel(const int* __restrict__ src,
                                                      const int* __restrict__ dst, int E) {
    int i = blockIdx.x * 256 + threadIdx.x;
    if (i >= E) return;
    int d = dst[i];
    int slot = g_rowptr[d] + atomicAdd(&g_cur[d], 1);
    g_perm[slot] = i;
    g_src_s[slot] = src[i];
    g_dst_s[slot] = d;
}

// ---------------- scores over sorted slots; warp per slot --------------------
__global__ __launch_bounds__(256) void scores_kernel(const float* __restrict__ ew, int E) {
    int slot = (blockIdx.x * 256 + threadIdx.x) >> 5;
    int lane = threadIdx.x & 31;
    if (slot >= E) return;
    int pe = g_perm[slot];
    int d = g_dst_s[slot];
    int s = g_src_s[slot];
    int h = lane >> 2, part = lane & 3;
    const float4* q4 = (const float4*)(g_q + (size_t)d * DMODEL + h * 32 + part * 8);
    const float4* k4 = (const float4*)(g_k + (size_t)s * DMODEL + h * 32 + part * 8);
    const float4* e4 = (const float4*)(g_ep + (size_t)pe * 32 + part * 8);
    float4 qa = q4[0], qb = q4[1];
    float4 ka = k4[0], kb = k4[1];
    float4 ea = e4[0], eb = e4[1];
    float p = qa.x * (ka.x + ea.x) + qa.y * (ka.y + ea.y)
            + qa.z * (ka.z + ea.z) + qa.w * (ka.w + ea.w)
            + qb.x * (kb.x + eb.x) + qb.y * (kb.y + eb.y)
            + qb.z * (kb.z + eb.z) + qb.w * (kb.w + eb.w);
    p += __shfl_xor_sync(0xFFFFFFFFu, p, 1);
    p += __shfl_xor_sync(0xFFFFFFFFu, p, 2);
    if (part == 0)
        g_sc[(size_t)slot * NHEAD + h] = p * ew[pe] * 0.17677669529663687f;
}

// ---------------- per-node softmax + aggregate (no atomics) ------------------
__global__ __launch_bounds__(256) void node_kernel(float* __restrict__ out_attn, int Nn) {
    int d = blockIdx.x;
    if (d >= Nn) return;
    int h = threadIdx.x >> 5, lane = threadIdx.x & 31;
    int b0 = g_rowptr[d], b1 = g_rowptr[d + 1];

    float m = -1e30f;
    for (int s = b0 + lane; s < b1; s += 32)
        m = fmaxf(m, g_sc[(size_t)s * NHEAD + h]);
    #pragma unroll
    for (int o = 16; o; o >>= 1) m = fmaxf(m, __shfl_xor_sync(0xFFFFFFFFu, m, o));

    float sum = 0.f;
    for (int s = b0 + lane; s < b1; s += 32) {
        float w = __expf(g_sc[(size_t)s * NHEAD + h] - m);
        g_sc[(size_t)s * NHEAD + h] = w;
        sum += w;
    }
    #pragma unroll
    for (int o = 16; o; o >>= 1) sum += __shfl_xor_sync(0xFFFFFFFFu, sum, o);
    float inv = 1.f / sum;

    float acc = 0.f;
    for (int s = b0; s < b1; s++) {
        float w = g_sc[(size_t)s * NHEAD + h] * inv;   // broadcast load
        int sn = g_src_s[s];                            // broadcast load
        acc += w * g_v[(size_t)sn * DMODEL + h * 32 + lane];
    }
    g_agg[(size_t)d * DMODEL + h * 32 + lane] = acc;

    for (int s = b0 + lane; s < b1; s += 32)
        out_attn[(size_t)g_perm[s] * NHEAD + h] = g_sc[(size_t)s * NHEAD + h] * inv;
}

// ---------------- host launcher ---------------------------------------------
static float* sym_addr(const void* symbol) {
    void* p = nullptr;
    cudaGetSymbolAddress(&p, symbol);
    return (float*)p;
}

extern "C" void kernel_launch(void* const* d_in, const int* in_sizes, int n_in,
                              void* d_out, int out_size) {
    const float* x  = (const float*)d_in[0];
    const int*   ei = (const int*)d_in[1];
    const float* ef = (const float*)d_in[2];
    const float* ew = (const float*)d_in[3];
    const float* Wq = (const float*)d_in[4];
    const float* bq = (const float*)d_in[5];
    const float* Wk = (const float*)d_in[6];
    const float* bk = (const float*)d_in[7];
    const float* Wv = (const float*)d_in[8];
    const float* bv = (const float*)d_in[9];
    const float* We = (const float*)d_in[10];
    const float* be = (const float*)d_in[11];
    const float* Wo = (const float*)d_in[12];
    const float* bo = (const float*)d_in[13];
    const float* W1 = (const float*)d_in[14];
    const float* b1 = (const float*)d_in[15];
    const float* W2 = (const float*)d_in[16];
    const float* b2 = (const float*)d_in[17];
    const float* g1 = (const float*)d_in[18];
    const float* be1 = (const float*)d_in[19];
    const float* g2 = (const float*)d_in[20];
    const float* be2 = (const float*)d_in[21];
    const float* alpha = (const float*)d_in[22];
    const float* beta  = (const float*)d_in[23];

    int Nn = in_sizes[0] / DMODEL;
    int E  = in_sizes[1] / 2;
    const int* src = ei;
    const int* dst = ei + E;

    float* out_x    = (float*)d_out;
    float* out_attn = out_x + (size_t)Nn * DMODEL;

    float* xn  = sym_addr(g_xn);
    float* q   = sym_addr(g_q);
    float* k   = sym_addr(g_k);
    float* v   = sym_addr(g_v);
    float* agg = sym_addr(g_agg);
    float* x1  = sym_addr(g_x1);
    float* xn2 = sym_addr(g_xn2);
    float* ff  = sym_addr(g_ff);

    cudaFuncSetAttribute(gemm_tc<0>, cudaFuncAttributeMaxDynamicSharedMemorySize, SMEM_BYTES);
    cudaFuncSetAttribute(gemm_tc<1>, cudaFuncAttributeMaxDynamicSharedMemorySize, SMEM_BYTES);
    cudaFuncSetAttribute(gemm_tc<2>, cudaFuncAttributeMaxDynamicSharedMemorySize, SMEM_BYTES);

    int gy = (Nn + TBM - 1) / TBM;

    // CSR build + LN1 + projections
    init_kernel<<<(Nn + 255) / 256, 256>>>(Nn);
    ln_kernel<<<(Nn * 32 + 255) / 256, 256>>>(x, g1, be1, xn, Nn);
    {
        dim3 grid(DMODEL / TBN, gy);
        gemm_tc<0><<<grid, 256, SMEM_BYTES>>>(xn, Wq, bq, nullptr, nullptr, q, Nn, DMODEL, DMODEL);
        gemm_tc<0><<<grid, 256, SMEM_BYTES>>>(xn, Wk, bk, nullptr, nullptr, k, Nn, DMODEL, DMODEL);
        gemm_tc<0><<<grid, 256, SMEM_BYTES>>>(xn, Wv, bv, nullptr, nullptr, v, Nn, DMODEL, DMODEL);
    }
    ep_kernel<<<4096, 256>>>(ef, We, be, E);
    hist_kernel<<<(E + 255) / 256, 256>>>(dst, E);
    scan_kernel<<<1, 1024>>>(Nn, E);
    scatter_kernel<<<(E + 255) / 256, 256>>>(src, dst, E);
    scores_kernel<<<(E * 32 + 255) / 256, 256>>>(ew, E);
    node_kernel<<<Nn, 256>>>(out_attn, Nn);
    // output projection + residual -> x1
    {
        dim3 grid(DMODEL / TBN, gy);
        gemm_tc<2><<<grid, 256, SMEM_BYTES>>>(agg, Wo, bo, x, alpha, x1, Nn, DMODEL, DMODEL);
    }
    ln_kernel<<<(Nn * 32 + 255) / 256, 256>>>(x1, g2, be2, xn2, Nn);
    // FF
    {
        dim3 grid((4 * DMODEL) / TBN, gy);
        gemm_tc<1><<<grid, 256, SMEM_BYTES>>>(xn2, W1, b1, nullptr, nullptr, ff, Nn, 4 * DMODEL, DMODEL);
    }
    {
        dim3 grid(DMODEL / TBN, gy);
        gemm_tc<2><<<grid, 256, SMEM_BYTES>>>(ff, W2, b2, x1, beta, out_x, Nn, DMODEL, 4 * DMODEL);
    }
}

// round 6
// speedup vs baseline: 2.4791x; 1.1712x over previous
#include <cuda_runtime.h>
#include <cuda_bf16.h>
#include <math.h>

#define NMAX 50000
#define EMAX 1600000
#define DMODEL 256
#define NHEAD 8
#define HD 32

// ---------------- scratch (static device globals; no allocation) -------------
__device__ float g_xn  [(size_t)NMAX * DMODEL];
__device__ float g_q   [(size_t)NMAX * DMODEL];
__device__ float g_k   [(size_t)NMAX * DMODEL];
__device__ float g_v   [(size_t)NMAX * DMODEL];
__device__ float g_ep  [(size_t)EMAX * HD];
__device__ float g_sc  [(size_t)NHEAD * EMAX];   // [head][slot] transposed
__device__ float g_agg [(size_t)NMAX * DMODEL];
__device__ float g_x1  [(size_t)NMAX * DMODEL];
__device__ float g_xn2 [(size_t)NMAX * DMODEL];
__device__ float g_ff  [(size_t)NMAX * 4 * DMODEL];
// CSR build
__device__ int g_cnt   [NMAX];
__device__ int g_cur   [NMAX];
__device__ int g_rowptr[NMAX + 1];
__device__ int g_perm  [EMAX];
__device__ int g_src_s [EMAX];
__device__ int g_dst_s [EMAX];

__device__ __forceinline__ unsigned smem_u32(const void* p) {
    return (unsigned)__cvta_generic_to_shared(p);
}
__device__ __forceinline__ void cp_async16(unsigned daddr, const void* gptr, int szbytes) {
    asm volatile("cp.async.cg.shared.global [%0], [%1], 16, %2;\n"
                 :: "r"(daddr), "l"(gptr), "r"(szbytes));
}

// ---------------- init: zero CSR counters -----------------------------------
__global__ __launch_bounds__(256) void init_kernel(int Nn) {
    int i = blockIdx.x * 256 + threadIdx.x;
    if (i < Nn) { g_cnt[i] = 0; g_cur[i] = 0; }
}

// ---------------- LayerNorm: one warp per node ------------------------------
__global__ __launch_bounds__(256) void ln_kernel(const float* __restrict__ x,
                                                 const float* __restrict__ g,
                                                 const float* __restrict__ b,
                                                 float* __restrict__ out, int Nn) {
    int warp = (blockIdx.x * 256 + threadIdx.x) >> 5;
    int lane = threadIdx.x & 31;
    if (warp >= Nn) return;
    const float4* xr = (const float4*)(x + (size_t)warp * DMODEL);
    float4 a = xr[lane];
    float4 c = xr[lane + 32];
    float s = a.x + a.y + a.z + a.w + c.x + c.y + c.z + c.w;
    float q = a.x*a.x + a.y*a.y + a.z*a.z + a.w*a.w
            + c.x*c.x + c.y*c.y + c.z*c.z + c.w*c.w;
    #pragma unroll
    for (int o = 16; o; o >>= 1) {
        s += __shfl_xor_sync(0xFFFFFFFFu, s, o);
        q += __shfl_xor_sync(0xFFFFFFFFu, q, o);
    }
    float mu = s * (1.f / 256.f);
    float var = q * (1.f / 256.f) - mu * mu;
    float inv = rsqrtf(var + 1e-5f);
    float4 g0 = ((const float4*)g)[lane], g1 = ((const float4*)g)[lane + 32];
    float4 b0 = ((const float4*)b)[lane], b1 = ((const float4*)b)[lane + 32];
    float4 o0, o1;
    o0.x = (a.x - mu) * inv * g0.x + b0.x;
    o0.y = (a.y - mu) * inv * g0.y + b0.y;
    o0.z = (a.z - mu) * inv * g0.z + b0.z;
    o0.w = (a.w - mu) * inv * g0.w + b0.w;
    o1.x = (c.x - mu) * inv * g1.x + b1.x;
    o1.y = (c.y - mu) * inv * g1.y + b1.y;
    o1.z = (c.z - mu) * inv * g1.z + b1.z;
    o1.w = (c.w - mu) * inv * g1.w + b1.w;
    float4* orow = (float4*)(out + (size_t)warp * DMODEL);
    orow[lane] = o0;
    orow[lane + 32] = o1;
}

// ---------------- tf32 TC GEMM: C = epi(A @ W^T + bias) ---------------------
// CTA tile 128x128, BK=32, cp.async double buffer. 8 warps, warp tile 32x64.
// launch_bounds(256,2) caps regs at 128 so 2 CTAs/SM fit (RF was the limiter).
#define TBM 128
#define TBN 128
#define TBK 32
#define SSTR 36
#define SMEM_WORDS (2 * (TBM + TBN) * SSTR)
#define SMEM_BYTES (SMEM_WORDS * 4)

__device__ __forceinline__ void mma_tf32(float c[4], const unsigned a[4], const unsigned b[2]) {
    asm volatile(
        "mma.sync.aligned.m16n8k8.row.col.f32.tf32.tf32.f32 "
        "{%0,%1,%2,%3},{%4,%5,%6,%7},{%8,%9},{%0,%1,%2,%3};\n"
        : "+f"(c[0]), "+f"(c[1]), "+f"(c[2]), "+f"(c[3])
        : "r"(a[0]), "r"(a[1]), "r"(a[2]), "r"(a[3]), "r"(b[0]), "r"(b[1]));
}

template <int EPI>
__global__ __launch_bounds__(256, 2) void gemm_tc(
    const float* __restrict__ A, const float* __restrict__ W,
    const float* __restrict__ bias, const float* __restrict__ R,
    const float* __restrict__ scl, float* __restrict__ C,
    int M, int N, int K) {
    extern __shared__ unsigned smem[];
    unsigned* As = smem;                       // [2][TBM*SSTR]
    unsigned* Bs = smem + 2 * TBM * SSTR;      // [2][TBN*SSTR]
    const unsigned sAb = smem_u32(As);
    const unsigned sBb = smem_u32(Bs);
    const int tid = threadIdx.x;
    const int m0 = blockIdx.y * TBM;
    const int n0 = blockIdx.x * TBN;
    const int warp = tid >> 5, lane = tid & 31;
    const int wm = warp & 3, wn = warp >> 2;   // 32 rows, 64 cols per warp
    const int g = lane >> 2, t = lane & 3;

    float acc[2][8][4];
    #pragma unroll
    for (int mi = 0; mi < 2; mi++)
        #pragma unroll
        for (int ni = 0; ni < 8; ni++)
            #pragma unroll
            for (int j = 0; j < 4; j++) acc[mi][ni][j] = 0.f;

    auto stage = [&](int buf, int k0) {
        #pragma unroll
        for (int i = 0; i < 4; i++) {
            int ch = tid + i * 256;
            int r = ch >> 3, c4 = (ch & 7) * 4;
            int m = m0 + r;
            int ok = (m < M);
            const float* gp = A + (size_t)(ok ? m : 0) * K + k0 + c4;
            cp_async16(sAb + (unsigned)(buf * TBM * SSTR + r * SSTR + c4) * 4, gp, ok ? 16 : 0);
        }
        #pragma unroll
        for (int i = 0; i < 4; i++) {
            int ch = tid + i * 256;
            int r = ch >> 3, c4 = (ch & 7) * 4;
            const float* gp = W + (size_t)(n0 + r) * K + k0 + c4;
            cp_async16(sBb + (unsigned)(buf * TBN * SSTR + r * SSTR + c4) * 4, gp, 16);
        }
        asm volatile("cp.async.commit_group;\n");
    };

    auto compute = [&](int buf) {
        const unsigned* Ab = As + buf * TBM * SSTR;
        const unsigned* Bb = Bs + buf * TBN * SSTR;
        #pragma unroll
        for (int ks = 0; ks < 4; ks++) {
            int k = ks * 8;
            unsigned af[2][4], bf[8][2];
            #pragma unroll
            for (int mi = 0; mi < 2; mi++) {
                int r = wm * 32 + mi * 16;
                af[mi][0] = Ab[(r + g) * SSTR + k + t];
                af[mi][1] = Ab[(r + g + 8) * SSTR + k + t];
                af[mi][2] = Ab[(r + g) * SSTR + k + t + 4];
                af[mi][3] = Ab[(r + g + 8) * SSTR + k + t + 4];
            }
            #pragma unroll
            for (int ni = 0; ni < 8; ni++) {
                int c = wn * 64 + ni * 8 + g;
                bf[ni][0] = Bb[c * SSTR + k + t];
                bf[ni][1] = Bb[c * SSTR + k + t + 4];
            }
            #pragma unroll
            for (int mi = 0; mi < 2; mi++)
                #pragma unroll
                for (int ni = 0; ni < 8; ni++)
                    mma_tf32(acc[mi][ni], af[mi], bf[ni]);
        }
    };

    const int nk = K / TBK;
    stage(0, 0);
    int buf = 0;
    for (int kt = 0; kt < nk; kt++) {
        if (kt + 1 < nk) {
            stage(buf ^ 1, (kt + 1) * TBK);
            asm volatile("cp.async.wait_group 1;\n");
        } else {
            asm volatile("cp.async.wait_group 0;\n");
        }
        __syncthreads();
        compute(buf);
        __syncthreads();
        buf ^= 1;
    }

    // epilogue: c0=(g,2t) c1=(g,2t+1) c2=(g+8,2t) c3=(g+8,2t+1)
    float al = (EPI == 2) ? scl[0] : 0.f;
    #pragma unroll
    for (int mi = 0; mi < 2; mi++) {
        #pragma unroll
        for (int ni = 0; ni < 8; ni++) {
            int col = n0 + wn * 64 + ni * 8 + 2 * t;
            float bx = bias[col], by = bias[col + 1];
            #pragma unroll
            for (int h = 0; h < 2; h++) {
                int row = m0 + wm * 32 + mi * 16 + g + h * 8;
                if (row >= M) continue;
                float v0 = acc[mi][ni][h * 2 + 0] + bx;
                float v1 = acc[mi][ni][h * 2 + 1] + by;
                if (EPI == 1) {
                    v0 = 0.5f * v0 * (1.f + erff(v0 * 0.70710678118654752f));
                    v1 = 0.5f * v1 * (1.f + erff(v1 * 0.70710678118654752f));
                }
                if (EPI == 2) {
                    const float* rr = R + (size_t)row * N + col;
                    v0 = rr[0] + al * v0;
                    v1 = rr[1] + al * v1;
                }
                *(float2*)(C + (size_t)row * N + col) = make_float2(v0, v1);
            }
        }
    }
}

// ---------------- edge projection: ep[E,32] = ef[E,32] @ We^T + be ----------
// We row held in registers; ef row broadcast from smem.
__global__ __launch_bounds__(256) void ep_kernel(const float* __restrict__ ef,
                                                 const float* __restrict__ We,
                                                 const float* __restrict__ be,
                                                 int E) {
    __shared__ float sWt[32 * 32];  // sWt[i*32+j] = We[j*32+i]
    __shared__ float sEf[8][33];
    int tid = threadIdx.x;
    for (int t = tid; t < 1024; t += 256) {
        int j = t >> 5, i = t & 31;
        sWt[i * 32 + j] = We[t];
    }
    __syncthreads();
    int el = tid >> 5, j = tid & 31;
    float wcol[32];
    #pragma unroll
    for (int i = 0; i < 32; i++) wcol[i] = sWt[i * 32 + j];  // conflict-free
    float bj = be[j];
    for (int e0 = blockIdx.x * 8; e0 < E; e0 += gridDim.x * 8) {
        int e = e0 + el;
        __syncthreads();
        if (e < E) sEf[el][j] = ef[(size_t)e * 32 + j];
        __syncthreads();
        if (e < E) {
            float s = bj;
            #pragma unroll
            for (int i = 0; i < 32; i++) s += sEf[el][i] * wcol[i];
            g_ep[(size_t)e * 32 + j] = s;
        }
    }
}

// ---------------- CSR build --------------------------------------------------
__global__ __launch_bounds__(256) void hist_kernel(const int* __restrict__ dst, int E) {
    int i = blockIdx.x * 256 + threadIdx.x;
    if (i < E) atomicAdd(&g_cnt[dst[i]], 1);
}

__global__ __launch_bounds__(1024) void scan_kernel(int Nn, int E) {
    const int tid = threadIdx.x;
    const int lane = tid & 31, wid = tid >> 5;
    __shared__ int warp_sums[32];
    __shared__ int carry;
    if (tid == 0) carry = 0;
    __syncthreads();
    for (int base = 0; base < Nn; base += 1024) {
        int i = base + tid;
        int v = (i < Nn) ? g_cnt[i] : 0;
        int x = v;
        #pragma unroll
        for (int o = 1; o < 32; o <<= 1) {
            int y = __shfl_up_sync(0xFFFFFFFFu, x, o);
            if (lane >= o) x += y;
        }
        if (lane == 31) warp_sums[wid] = x;
        __syncthreads();
        if (wid == 0) {
            int s = warp_sums[lane];
            #pragma unroll
            for (int o = 1; o < 32; o <<= 1) {
                int y = __shfl_up_sync(0xFFFFFFFFu, s, o);
                if (lane >= o) s += y;
            }
            warp_sums[lane] = s;
        }
        __syncthreads();
        int offset = carry + (wid ? warp_sums[wid - 1] : 0);
        if (i < Nn) g_rowptr[i] = offset + x - v;
        int blocktotal = warp_sums[31];
        __syncthreads();
        if (tid == 0) carry += blocktotal;
        __syncthreads();
    }
    if (tid == 0) g_rowptr[Nn] = E;
}

__global__ __launch_bounds__(256) void scatter_kernel(const int* __restrict__ src,
                                                      const int* __restrict__ dst, int E) {
    int i = blockIdx.x * 256 + threadIdx.x;
    if (i >= E) return;
    int d = dst[i];
    int slot = g_rowptr[d] + atomicAdd(&g_cur[d], 1);
    g_perm[slot] = i;
    g_src_s[slot] = src[i];
    g_dst_s[slot] = d;
}

// ---------------- scores over sorted slots; warp per slot --------------------
__global__ __launch_bounds__(256) void scores_kernel(const float* __restrict__ ew, int E) {
    int slot = (blockIdx.x * 256 + threadIdx.x) >> 5;
    int lane = threadIdx.x & 31;
    if (slot >= E) return;
    int pe = g_perm[slot];
    int d = g_dst_s[slot];
    int s = g_src_s[slot];
    int h = lane >> 2, part = lane & 3;
    const float4* q4 = (const float4*)(g_q + (size_t)d * DMODEL + h * 32 + part * 8);
    const float4* k4 = (const float4*)(g_k + (size_t)s * DMODEL + h * 32 + part * 8);
    const float4* e4 = (const float4*)(g_ep + (size_t)pe * 32 + part * 8);
    float4 qa = q4[0], qb = q4[1];
    float4 ka = k4[0], kb = k4[1];
    float4 ea = e4[0], eb = e4[1];
    float p = qa.x * (ka.x + ea.x) + qa.y * (ka.y + ea.y)
            + qa.z * (ka.z + ea.z) + qa.w * (ka.w + ea.w)
            + qb.x * (kb.x + eb.x) + qb.y * (kb.y + eb.y)
            + qb.z * (kb.z + eb.z) + qb.w * (kb.w + eb.w);
    p += __shfl_xor_sync(0xFFFFFFFFu, p, 1);
    p += __shfl_xor_sync(0xFFFFFFFFu, p, 2);
    if (part == 0)
        g_sc[(size_t)h * EMAX + slot] = p * ew[pe] * 0.17677669529663687f;
}

// ---------------- per-node softmax + aggregate (no atomics) ------------------
__global__ __launch_bounds__(256) void node_kernel(float* __restrict__ out_attn, int Nn) {
    int d = blockIdx.x;
    if (d >= Nn) return;
    int h = threadIdx.x >> 5, lane = threadIdx.x & 31;
    int b0 = g_rowptr[d], b1 = g_rowptr[d + 1];
    float* schead = g_sc + (size_t)h * EMAX;

    float m = -1e30f;
    for (int s = b0 + lane; s < b1; s += 32)
        m = fmaxf(m, schead[s]);                      // coalesced
    #pragma unroll
    for (int o = 16; o; o >>= 1) m = fmaxf(m, __shfl_xor_sync(0xFFFFFFFFu, m, o));

    float sum = 0.f;
    for (int s = b0 + lane; s < b1; s += 32) {
        float w = __expf(schead[s] - m);
        schead[s] = w;
        sum += w;
    }
    #pragma unroll
    for (int o = 16; o; o >>= 1) sum += __shfl_xor_sync(0xFFFFFFFFu, sum, o);
    float inv = 1.f / sum;

    float a0 = 0.f, a1 = 0.f, a2 = 0.f, a3 = 0.f;
    const float* vbase = g_v + h * 32 + lane;
    for (int s0 = b0; s0 < b1; s0 += 32) {
        int n = min(32, b1 - s0);
        float w = 0.f; int sn = 0;
        if (lane < n) {
            w = schead[s0 + lane] * inv;
            sn = g_src_s[s0 + lane];
            out_attn[(size_t)g_perm[s0 + lane] * NHEAD + h] = w;
        }
        int j = 0;
        for (; j + 4 <= n; j += 4) {
            float w0 = __shfl_sync(0xFFFFFFFFu, w, j + 0);
            float w1 = __shfl_sync(0xFFFFFFFFu, w, j + 1);
            float w2 = __shfl_sync(0xFFFFFFFFu, w, j + 2);
            float w3 = __shfl_sync(0xFFFFFFFFu, w, j + 3);
            int i0 = __shfl_sync(0xFFFFFFFFu, sn, j + 0);
            int i1 = __shfl_sync(0xFFFFFFFFu, sn, j + 1);
            int i2 = __shfl_sync(0xFFFFFFFFu, sn, j + 2);
            int i3 = __shfl_sync(0xFFFFFFFFu, sn, j + 3);
            a0 += w0 * vbase[(size_t)i0 * DMODEL];
            a1 += w1 * vbase[(size_t)i1 * DMODEL];
            a2 += w2 * vbase[(size_t)i2 * DMODEL];
            a3 += w3 * vbase[(size_t)i3 * DMODEL];
        }
        for (; j < n; j++) {
            float wj = __shfl_sync(0xFFFFFFFFu, w, j);
            int ij = __shfl_sync(0xFFFFFFFFu, sn, j);
            a0 += wj * vbase[(size_t)ij * DMODEL];
        }
    }
    g_agg[(size_t)d * DMODEL + h * 32 + lane] = (a0 + a1) + (a2 + a3);
}

// ---------------- host launcher ---------------------------------------------
static float* sym_addr(const void* symbol) {
    void* p = nullptr;
    cudaGetSymbolAddress(&p, symbol);
    return (float*)p;
}

extern "C" void kernel_launch(void* const* d_in, const int* in_sizes, int n_in,
                              void* d_out, int out_size) {
    const float* x  = (const float*)d_in[0];
    const int*   ei = (const int*)d_in[1];
    const float* ef = (const float*)d_in[2];
    const float* ew = (const float*)d_in[3];
    const float* Wq = (const float*)d_in[4];
    const float* bq = (const float*)d_in[5];
    const float* Wk = (const float*)d_in[6];
    const float* bk = (const float*)d_in[7];
    const float* Wv = (const float*)d_in[8];
    const float* bv = (const float*)d_in[9];
    const float* We = (const float*)d_in[10];
    const float* be = (const float*)d_in[11];
    const float* Wo = (const float*)d_in[12];
    const float* bo = (const float*)d_in[13];
    const float* W1 = (const float*)d_in[14];
    const float* b1 = (const float*)d_in[15];
    const float* W2 = (const float*)d_in[16];
    const float* b2 = (const float*)d_in[17];
    const float* g1 = (const float*)d_in[18];
    const float* be1 = (const float*)d_in[19];
    const float* g2 = (const float*)d_in[20];
    const float* be2 = (const float*)d_in[21];
    const float* alpha = (const float*)d_in[22];
    const float* beta  = (const float*)d_in[23];

    int Nn = in_sizes[0] / DMODEL;
    int E  = in_sizes[1] / 2;
    const int* src = ei;
    const int* dst = ei + E;

    float* out_x    = (float*)d_out;
    float* out_attn = out_x + (size_t)Nn * DMODEL;

    float* xn  = sym_addr(g_xn);
    float* q   = sym_addr(g_q);
    float* k   = sym_addr(g_k);
    float* v   = sym_addr(g_v);
    float* agg = sym_addr(g_agg);
    float* x1  = sym_addr(g_x1);
    float* xn2 = sym_addr(g_xn2);
    float* ff  = sym_addr(g_ff);

    cudaFuncSetAttribute(gemm_tc<0>, cudaFuncAttributeMaxDynamicSharedMemorySize, SMEM_BYTES);
    cudaFuncSetAttribute(gemm_tc<1>, cudaFuncAttributeMaxDynamicSharedMemorySize, SMEM_BYTES);
    cudaFuncSetAttribute(gemm_tc<2>, cudaFuncAttributeMaxDynamicSharedMemorySize, SMEM_BYTES);

    int gy = (Nn + TBM - 1) / TBM;

    // CSR build + LN1 + projections
    init_kernel<<<(Nn + 255) / 256, 256>>>(Nn);
    ln_kernel<<<(Nn * 32 + 255) / 256, 256>>>(x, g1, be1, xn, Nn);
    {
        dim3 grid(DMODEL / TBN, gy);
        gemm_tc<0><<<grid, 256, SMEM_BYTES>>>(xn, Wq, bq, nullptr, nullptr, q, Nn, DMODEL, DMODEL);
        gemm_tc<0><<<grid, 256, SMEM_BYTES>>>(xn, Wk, bk, nullptr, nullptr, k, Nn, DMODEL, DMODEL);
        gemm_tc<0><<<grid, 256, SMEM_BYTES>>>(xn, Wv, bv, nullptr, nullptr, v, Nn, DMODEL, DMODEL);
    }
    ep_kernel<<<4096, 256>>>(ef, We, be, E);
    hist_kernel<<<(E + 255) / 256, 256>>>(dst, E);
    scan_kernel<<<1, 1024>>>(Nn, E);
    scatter_kernel<<<(E + 255) / 256, 256>>>(src, dst, E);
    scores_kernel<<<(E * 32 + 255) / 256, 256>>>(ew, E);
    node_kernel<<<Nn, 256>>>(out_attn, Nn);
    // output projection + residual -> x1
    {
        dim3 grid(DMODEL / TBN, gy);
        gemm_tc<2><<<grid, 256, SMEM_BYTES>>>(agg, Wo, bo, x, alpha, x1, Nn, DMODEL, DMODEL);
    }
    ln_kernel<<<(Nn * 32 + 255) / 256, 256>>>(x1, g2, be2, xn2, Nn);
    // FF
    {
        dim3 grid((4 * DMODEL) / TBN, gy);
        gemm_tc<1><<<grid, 256, SMEM_BYTES>>>(xn2, W1, b1, nullptr, nullptr, ff, Nn, 4 * DMODEL, DMODEL);
    }
    {
        dim3 grid(DMODEL / TBN, gy);
        gemm_tc<2><<<grid, 256, SMEM_BYTES>>>(ff, W2, b2, x1, beta, out_x, Nn, DMODEL, 4 * DMODEL);
    }
}

// round 7
// speedup vs baseline: 2.6021x; 1.0496x over previous
#include <cuda_runtime.h>
#include <cuda_bf16.h>
#include <math.h>

#define NMAX 50000
#define EMAX 1600000
#define DMODEL 256
#define NHEAD 8
#define HD 32

// ---------------- scratch (static device globals; no allocation) -------------
__device__ float g_xn  [(size_t)NMAX * DMODEL];
__device__ float g_q   [(size_t)NMAX * DMODEL];
__device__ float g_k   [(size_t)NMAX * DMODEL];
__device__ float g_v   [(size_t)NMAX * DMODEL];
__device__ float g_ep  [(size_t)EMAX * HD];
__device__ float g_sc  [(size_t)NHEAD * EMAX];   // [head][slot] transposed
__device__ float g_agg [(size_t)NMAX * DMODEL];
__device__ float g_x1  [(size_t)NMAX * DMODEL];
__device__ float g_xn2 [(size_t)NMAX * DMODEL];
__device__ float g_ff  [(size_t)NMAX * 4 * DMODEL];
// CSR build
__device__ int g_cnt   [NMAX];
__device__ int g_cur   [NMAX];
__device__ int g_rowptr[NMAX + 1];
__device__ int g_perm  [EMAX];
__device__ int g_src_s [EMAX];
__device__ int g_dst_s [EMAX];

__device__ __forceinline__ unsigned smem_u32(const void* p) {
    return (unsigned)__cvta_generic_to_shared(p);
}
__device__ __forceinline__ void cp_async16(unsigned daddr, const void* gptr, int szbytes) {
    asm volatile("cp.async.cg.shared.global [%0], [%1], 16, %2;\n"
                 :: "r"(daddr), "l"(gptr), "r"(szbytes));
}

// ---------------- init: zero CSR counters -----------------------------------
__global__ __launch_bounds__(256) void init_kernel(int Nn) {
    int i = blockIdx.x * 256 + threadIdx.x;
    if (i < Nn) { g_cnt[i] = 0; g_cur[i] = 0; }
}

// ---------------- LayerNorm: one warp per node ------------------------------
__global__ __launch_bounds__(256) void ln_kernel(const float* __restrict__ x,
                                                 const float* __restrict__ g,
                                                 const float* __restrict__ b,
                                                 float* __restrict__ out, int Nn) {
    int warp = (blockIdx.x * 256 + threadIdx.x) >> 5;
    int lane = threadIdx.x & 31;
    if (warp >= Nn) return;
    const float4* xr = (const float4*)(x + (size_t)warp * DMODEL);
    float4 a = xr[lane];
    float4 c = xr[lane + 32];
    float s = a.x + a.y + a.z + a.w + c.x + c.y + c.z + c.w;
    float q = a.x*a.x + a.y*a.y + a.z*a.z + a.w*a.w
            + c.x*c.x + c.y*c.y + c.z*c.z + c.w*c.w;
    #pragma unroll
    for (int o = 16; o; o >>= 1) {
        s += __shfl_xor_sync(0xFFFFFFFFu, s, o);
        q += __shfl_xor_sync(0xFFFFFFFFu, q, o);
    }
    float mu = s * (1.f / 256.f);
    float var = q * (1.f / 256.f) - mu * mu;
    float inv = rsqrtf(var + 1e-5f);
    float4 g0 = ((const float4*)g)[lane], g1 = ((const float4*)g)[lane + 32];
    float4 b0 = ((const float4*)b)[lane], b1 = ((const float4*)b)[lane + 32];
    float4 o0, o1;
    o0.x = (a.x - mu) * inv * g0.x + b0.x;
    o0.y = (a.y - mu) * inv * g0.y + b0.y;
    o0.z = (a.z - mu) * inv * g0.z + b0.z;
    o0.w = (a.w - mu) * inv * g0.w + b0.w;
    o1.x = (c.x - mu) * inv * g1.x + b1.x;
    o1.y = (c.y - mu) * inv * g1.y + b1.y;
    o1.z = (c.z - mu) * inv * g1.z + b1.z;
    o1.w = (c.w - mu) * inv * g1.w + b1.w;
    float4* orow = (float4*)(out + (size_t)warp * DMODEL);
    orow[lane] = o0;
    orow[lane + 32] = o1;
}

// ---------------- tf32 TC GEMM core: C = epi(A @ W^T + bias) ----------------
// CTA tile 128x128, BK=32, 3-stage cp.async pipeline, ONE syncthreads/iter.
#define TBM 128
#define TBN 128
#define TBK 32
#define SSTR 36
#define BUFW ((TBM + TBN) * SSTR)
#define SMEM_BYTES (3 * BUFW * 4)

__device__ __forceinline__ void mma_tf32(float c[4], const unsigned a[4], const unsigned b[2]) {
    asm volatile(
        "mma.sync.aligned.m16n8k8.row.col.f32.tf32.tf32.f32 "
        "{%0,%1,%2,%3},{%4,%5,%6,%7},{%8,%9},{%0,%1,%2,%3};\n"
        : "+f"(c[0]), "+f"(c[1]), "+f"(c[2]), "+f"(c[3])
        : "r"(a[0]), "r"(a[1]), "r"(a[2]), "r"(a[3]), "r"(b[0]), "r"(b[1]));
}

template <int EPI>
__device__ __forceinline__ void gemm_core(
    const float* __restrict__ A, const float* __restrict__ W,
    const float* __restrict__ bias, const float* __restrict__ R,
    const float* __restrict__ scl, float* __restrict__ C,
    int M, int N, int K, int m0, int n0) {
    extern __shared__ unsigned smem[];
    const unsigned sBase = smem_u32(smem);
    const int tid = threadIdx.x;
    const int warp = tid >> 5, lane = tid & 31;
    const int wm = warp & 3, wn = warp >> 2;   // 32 rows, 64 cols per warp
    const int g = lane >> 2, t = lane & 3;

    float acc[2][8][4];
    #pragma unroll
    for (int mi = 0; mi < 2; mi++)
        #pragma unroll
        for (int ni = 0; ni < 8; ni++)
            #pragma unroll
            for (int j = 0; j < 4; j++) acc[mi][ni][j] = 0.f;

    auto stage = [&](int buf, int k0) {
        unsigned base = sBase + (unsigned)(buf * BUFW) * 4;
        #pragma unroll
        for (int i = 0; i < 4; i++) {
            int ch = tid + i * 256;
            int r = ch >> 3, c4 = (ch & 7) * 4;
            int m = m0 + r;
            int ok = (m < M);
            const float* gp = A + (size_t)(ok ? m : 0) * K + k0 + c4;
            cp_async16(base + (unsigned)(r * SSTR + c4) * 4, gp, ok ? 16 : 0);
        }
        #pragma unroll
        for (int i = 0; i < 4; i++) {
            int ch = tid + i * 256;
            int r = ch >> 3, c4 = (ch & 7) * 4;
            const float* gp = W + (size_t)(n0 + r) * K + k0 + c4;
            cp_async16(base + (unsigned)(TBM * SSTR + r * SSTR + c4) * 4, gp, 16);
        }
        asm volatile("cp.async.commit_group;\n");
    };

    auto compute = [&](int buf) {
        const unsigned* Ab = smem + buf * BUFW;
        const unsigned* Bb = Ab + TBM * SSTR;
        #pragma unroll
        for (int ks = 0; ks < 4; ks++) {
            int k = ks * 8;
            unsigned af[2][4], bf[8][2];
            #pragma unroll
            for (int mi = 0; mi < 2; mi++) {
                int r = wm * 32 + mi * 16;
                af[mi][0] = Ab[(r + g) * SSTR + k + t];
                af[mi][1] = Ab[(r + g + 8) * SSTR + k + t];
                af[mi][2] = Ab[(r + g) * SSTR + k + t + 4];
                af[mi][3] = Ab[(r + g + 8) * SSTR + k + t + 4];
            }
            #pragma unroll
            for (int ni = 0; ni < 8; ni++) {
                int c = wn * 64 + ni * 8 + g;
                bf[ni][0] = Bb[c * SSTR + k + t];
                bf[ni][1] = Bb[c * SSTR + k + t + 4];
            }
            #pragma unroll
            for (int mi = 0; mi < 2; mi++)
                #pragma unroll
                for (int ni = 0; ni < 8; ni++)
                    mma_tf32(acc[mi][ni], af[mi], bf[ni]);
        }
    };

    const int nk = K / TBK;
    stage(0, 0);
    stage(1, TBK);
    int buf = 0;
    for (int kt = 0; kt < nk; kt++) {
        if (kt + 1 < nk) asm volatile("cp.async.wait_group 1;\n");
        else             asm volatile("cp.async.wait_group 0;\n");
        __syncthreads();
        if (kt + 2 < nk) {
            int nb = buf + 2; if (nb >= 3) nb -= 3;
            stage(nb, (kt + 2) * TBK);
        }
        compute(buf);
        if (++buf == 3) buf = 0;
    }

    float al = (EPI == 2) ? scl[0] : 0.f;
    #pragma unroll
    for (int mi = 0; mi < 2; mi++) {
        #pragma unroll
        for (int ni = 0; ni < 8; ni++) {
            int col = n0 + wn * 64 + ni * 8 + 2 * t;
            float bx = bias[col], by = bias[col + 1];
            #pragma unroll
            for (int h = 0; h < 2; h++) {
                int row = m0 + wm * 32 + mi * 16 + g + h * 8;
                if (row >= M) continue;
                float v0 = acc[mi][ni][h * 2 + 0] + bx;
                float v1 = acc[mi][ni][h * 2 + 1] + by;
                if (EPI == 1) {
                    v0 = 0.5f * v0 * (1.f + erff(v0 * 0.70710678118654752f));
                    v1 = 0.5f * v1 * (1.f + erff(v1 * 0.70710678118654752f));
                }
                if (EPI == 2) {
                    const float* rr = R + (size_t)row * N + col;
                    v0 = rr[0] + al * v0;
                    v1 = rr[1] + al * v1;
                }
                *(float2*)(C + (size_t)row * N + col) = make_float2(v0, v1);
            }
        }
    }
}

template <int EPI>
__global__ __launch_bounds__(256, 2) void gemm_tc(
    const float* __restrict__ A, const float* __restrict__ W,
    const float* __restrict__ bias, const float* __restrict__ R,
    const float* __restrict__ scl, float* __restrict__ C,
    int M, int N, int K) {
    gemm_core<EPI>(A, W, bias, R, scl, C, M, N, K,
                   blockIdx.y * TBM, blockIdx.x * TBN);
}

// fused QKV: one launch, CTA selects matrix by blockIdx.x>>1
__global__ __launch_bounds__(256, 2) void gemm_qkv(
    const float* __restrict__ A,
    const float* __restrict__ Wq, const float* __restrict__ bq, float* __restrict__ q,
    const float* __restrict__ Wk, const float* __restrict__ bk, float* __restrict__ k,
    const float* __restrict__ Wv, const float* __restrict__ bv, float* __restrict__ v,
    int M) {
    int sel = blockIdx.x >> 1;
    int n0 = (blockIdx.x & 1) * TBN;
    const float* W = (sel == 0) ? Wq : (sel == 1) ? Wk : Wv;
    const float* b = (sel == 0) ? bq : (sel == 1) ? bk : bv;
    float* C       = (sel == 0) ? q  : (sel == 1) ? k  : v;
    gemm_core<0>(A, W, b, nullptr, nullptr, C, M, DMODEL, DMODEL,
                 blockIdx.y * TBM, n0);
}

// ---------------- edge projection: ep[E,32] = ef[E,32] @ We^T + be ----------
__global__ __launch_bounds__(256) void ep_kernel(const float* __restrict__ ef,
                                                 const float* __restrict__ We,
                                                 const float* __restrict__ be,
                                                 int E) {
    __shared__ float sWt[32 * 32];  // sWt[i*32+j] = We[j*32+i]
    __shared__ float sEf[8][33];
    int tid = threadIdx.x;
    for (int t = tid; t < 1024; t += 256) {
        int j = t >> 5, i = t & 31;
        sWt[i * 32 + j] = We[t];
    }
    __syncthreads();
    int el = tid >> 5, j = tid & 31;
    float wcol[32];
    #pragma unroll
    for (int i = 0; i < 32; i++) wcol[i] = sWt[i * 32 + j];
    float bj = be[j];
    for (int e0 = blockIdx.x * 8; e0 < E; e0 += gridDim.x * 8) {
        int e = e0 + el;
        __syncthreads();
        if (e < E) sEf[el][j] = ef[(size_t)e * 32 + j];
        __syncthreads();
        if (e < E) {
            float s = bj;
            #pragma unroll
            for (int i = 0; i < 32; i++) s += sEf[el][i] * wcol[i];
            g_ep[(size_t)e * 32 + j] = s;
        }
    }
}

// ---------------- CSR build --------------------------------------------------
__global__ __launch_bounds__(256) void hist_kernel(const int* __restrict__ dst, int E) {
    int i = blockIdx.x * 256 + threadIdx.x;
    if (i < E) atomicAdd(&g_cnt[dst[i]], 1);
}

__global__ __launch_bounds__(1024) void scan_kernel(int Nn, int E) {
    const int tid = threadIdx.x;
    const int lane = tid & 31, wid = tid >> 5;
    __shared__ int warp_sums[32];
    __shared__ int carry;
    if (tid == 0) carry = 0;
    __syncthreads();
    for (int base = 0; base < Nn; base += 1024) {
        int i = base + tid;
        int v = (i < Nn) ? g_cnt[i] : 0;
        int x = v;
        #pragma unroll
        for (int o = 1; o < 32; o <<= 1) {
            int y = __shfl_up_sync(0xFFFFFFFFu, x, o);
            if (lane >= o) x += y;
        }
        if (lane == 31) warp_sums[wid] = x;
        __syncthreads();
        if (wid == 0) {
            int s = warp_sums[lane];
            #pragma unroll
            for (int o = 1; o < 32; o <<= 1) {
                int y = __shfl_up_sync(0xFFFFFFFFu, s, o);
                if (lane >= o) s += y;
            }
            warp_sums[lane] = s;
        }
        __syncthreads();
        int offset = carry + (wid ? warp_sums[wid - 1] : 0);
        if (i < Nn) g_rowptr[i] = offset + x - v;
        int blocktotal = warp_sums[31];
        __syncthreads();
        if (tid == 0) carry += blocktotal;
        __syncthreads();
    }
    if (tid == 0) g_rowptr[Nn] = E;
}

__global__ __launch_bounds__(256) void scatter_kernel(const int* __restrict__ src,
                                                      const int* __restrict__ dst, int E) {
    int i = blockIdx.x * 256 + threadIdx.x;
    if (i >= E) return;
    int d = dst[i];
    int slot = g_rowptr[d] + atomicAdd(&g_cur[d], 1);
    g_perm[slot] = i;
    g_src_s[slot] = src[i];
    g_dst_s[slot] = d;
}

// ---------------- scores: warp per slot; smem-staged coalesced writes --------
__global__ __launch_bounds__(256) void scores_kernel(const float* __restrict__ ew, int E) {
    __shared__ float sSc[NHEAD][8];
    int warp = threadIdx.x >> 5;
    int lane = threadIdx.x & 31;
    int slot = blockIdx.x * 8 + warp;
    if (slot < E) {
        int pe = g_perm[slot];
        int d = g_dst_s[slot];
        int s = g_src_s[slot];
        int h = lane >> 2, part = lane & 3;
        const float4* q4 = (const float4*)(g_q + (size_t)d * DMODEL + h * 32 + part * 8);
        const float4* k4 = (const float4*)(g_k + (size_t)s * DMODEL + h * 32 + part * 8);
        const float4* e4 = (const float4*)(g_ep + (size_t)pe * 32 + part * 8);
        float4 qa = q4[0], qb = q4[1];
        float4 ka = k4[0], kb = k4[1];
        float4 ea = e4[0], eb = e4[1];
        float p = qa.x * (ka.x + ea.x) + qa.y * (ka.y + ea.y)
                + qa.z * (ka.z + ea.z) + qa.w * (ka.w + ea.w)
                + qb.x * (kb.x + eb.x) + qb.y * (kb.y + eb.y)
                + qb.z * (kb.z + eb.z) + qb.w * (kb.w + eb.w);
        p += __shfl_xor_sync(0xFFFFFFFFu, p, 1);
        p += __shfl_xor_sync(0xFFFFFFFFu, p, 2);
        if (part == 0)
            sSc[h][warp] = p * ew[pe] * 0.17677669529663687f;
    }
    __syncthreads();
    if (threadIdx.x < 64) {
        int h = threadIdx.x >> 3, i = threadIdx.x & 7;
        int si = blockIdx.x * 8 + i;
        if (si < E) g_sc[(size_t)h * EMAX + si] = sSc[h][i];  // 32B/row coalesced
    }
}

// ---------------- per-node softmax + aggregate (no atomics) ------------------
__global__ __launch_bounds__(256) void node_kernel(int Nn) {
    int d = blockIdx.x;
    if (d >= Nn) return;
    int h = threadIdx.x >> 5, lane = threadIdx.x & 31;
    int b0 = g_rowptr[d], b1 = g_rowptr[d + 1];
    float* schead = g_sc + (size_t)h * EMAX;

    float m = -1e30f;
    for (int s = b0 + lane; s < b1; s += 32)
        m = fmaxf(m, schead[s]);
    #pragma unroll
    for (int o = 16; o; o >>= 1) m = fmaxf(m, __shfl_xor_sync(0xFFFFFFFFu, m, o));

    float sum = 0.f;
    for (int s = b0 + lane; s < b1; s += 32) {
        float w = __expf(schead[s] - m);
        schead[s] = w;
        sum += w;
    }
    #pragma unroll
    for (int o = 16; o; o >>= 1) sum += __shfl_xor_sync(0xFFFFFFFFu, sum, o);
    float inv = 1.f / sum;

    float a0 = 0.f, a1 = 0.f, a2 = 0.f, a3 = 0.f;
    const float* vbase = g_v + h * 32 + lane;
    for (int s0 = b0; s0 < b1; s0 += 32) {
        int n = min(32, b1 - s0);
        float w = 0.f; int sn = 0;
        if (lane < n) {
            w = schead[s0 + lane] * inv;
            sn = g_src_s[s0 + lane];
            schead[s0 + lane] = w;      // normalized weight, coalesced
        }
        int j = 0;
        for (; j + 8 <= n; j += 8) {
            float w0 = __shfl_sync(0xFFFFFFFFu, w, j + 0);
            float w1 = __shfl_sync(0xFFFFFFFFu, w, j + 1);
            float w2 = __shfl_sync(0xFFFFFFFFu, w, j + 2);
            float w3 = __shfl_sync(0xFFFFFFFFu, w, j + 3);
            float w4 = __shfl_sync(0xFFFFFFFFu, w, j + 4);
            float w5 = __shfl_sync(0xFFFFFFFFu, w, j + 5);
            float w6 = __shfl_sync(0xFFFFFFFFu, w, j + 6);
            float w7 = __shfl_sync(0xFFFFFFFFu, w, j + 7);
            int i0 = __shfl_sync(0xFFFFFFFFu, sn, j + 0);
            int i1 = __shfl_sync(0xFFFFFFFFu, sn, j + 1);
            int i2 = __shfl_sync(0xFFFFFFFFu, sn, j + 2);
            int i3 = __shfl_sync(0xFFFFFFFFu, sn, j + 3);
            int i4 = __shfl_sync(0xFFFFFFFFu, sn, j + 4);
            int i5 = __shfl_sync(0xFFFFFFFFu, sn, j + 5);
            int i6 = __shfl_sync(0xFFFFFFFFu, sn, j + 6);
            int i7 = __shfl_sync(0xFFFFFFFFu, sn, j + 7);
            a0 += w0 * vbase[(size_t)i0 * DMODEL];
            a1 += w1 * vbase[(size_t)i1 * DMODEL];
            a2 += w2 * vbase[(size_t)i2 * DMODEL];
            a3 += w3 * vbase[(size_t)i3 * DMODEL];
            a0 += w4 * vbase[(size_t)i4 * DMODEL];
            a1 += w5 * vbase[(size_t)i5 * DMODEL];
            a2 += w6 * vbase[(size_t)i6 * DMODEL];
            a3 += w7 * vbase[(size_t)i7 * DMODEL];
        }
        for (; j < n; j++) {
            float wj = __shfl_sync(0xFFFFFFFFu, w, j);
            int ij = __shfl_sync(0xFFFFFFFFu, sn, j);
            a0 += wj * vbase[(size_t)ij * DMODEL];
        }
    }
    g_agg[(size_t)d * DMODEL + h * 32 + lane] = (a0 + a1) + (a2 + a3);
}

// ---------------- permute attn weights to original edge order ----------------
__global__ __launch_bounds__(256) void attn_out_kernel(float* __restrict__ out_attn, int E) {
    int e = blockIdx.x * 256 + threadIdx.x;
    if (e >= E) return;
    int orig = g_perm[e];
    float4 w0, w1;
    w0.x = g_sc[(size_t)0 * EMAX + e];
    w0.y = g_sc[(size_t)1 * EMAX + e];
    w0.z = g_sc[(size_t)2 * EMAX + e];
    w0.w = g_sc[(size_t)3 * EMAX + e];
    w1.x = g_sc[(size_t)4 * EMAX + e];
    w1.y = g_sc[(size_t)5 * EMAX + e];
    w1.z = g_sc[(size_t)6 * EMAX + e];
    w1.w = g_sc[(size_t)7 * EMAX + e];
    float4* op = (float4*)(out_attn + (size_t)orig * NHEAD);
    op[0] = w0;
    op[1] = w1;
}

// ---------------- host launcher ---------------------------------------------
static float* sym_addr(const void* symbol) {
    void* p = nullptr;
    cudaGetSymbolAddress(&p, symbol);
    return (float*)p;
}

extern "C" void kernel_launch(void* const* d_in, const int* in_sizes, int n_in,
                              void* d_out, int out_size) {
    const float* x  = (const float*)d_in[0];
    const int*   ei = (const int*)d_in[1];
    const float* ef = (const float*)d_in[2];
    const float* ew = (const float*)d_in[3];
    const float* Wq = (const float*)d_in[4];
    const float* bq = (const float*)d_in[5];
    const float* Wk = (const float*)d_in[6];
    const float* bk = (const float*)d_in[7];
    const float* Wv = (const float*)d_in[8];
    const float* bv = (const float*)d_in[9];
    const float* We = (const float*)d_in[10];
    const float* be = (const float*)d_in[11];
    const float* Wo = (const float*)d_in[12];
    const float* bo = (const float*)d_in[13];
    const float* W1 = (const float*)d_in[14];
    const float* b1 = (const float*)d_in[15];
    const float* W2 = (const float*)d_in[16];
    const float* b2 = (const float*)d_in[17];
    const float* g1 = (const float*)d_in[18];
    const float* be1 = (const float*)d_in[19];
    const float* g2 = (const float*)d_in[20];
    const float* be2 = (const float*)d_in[21];
    const float* alpha = (const float*)d_in[22];
    const float* beta  = (const float*)d_in[23];

    int Nn = in_sizes[0] / DMODEL;
    int E  = in_sizes[1] / 2;
    const int* src = ei;
    const int* dst = ei + E;

    float* out_x    = (float*)d_out;
    float* out_attn = out_x + (size_t)Nn * DMODEL;

    float* xn  = sym_addr(g_xn);
    float* q   = sym_addr(g_q);
    float* k   = sym_addr(g_k);
    float* v   = sym_addr(g_v);
    float* agg = sym_addr(g_agg);
    float* x1  = sym_addr(g_x1);
    float* xn2 = sym_addr(g_xn2);
    float* ff  = sym_addr(g_ff);

    cudaFuncSetAttribute(gemm_tc<0>, cudaFuncAttributeMaxDynamicSharedMemorySize, SMEM_BYTES);
    cudaFuncSetAttribute(gemm_tc<1>, cudaFuncAttributeMaxDynamicSharedMemorySize, SMEM_BYTES);
    cudaFuncSetAttribute(gemm_tc<2>, cudaFuncAttributeMaxDynamicSharedMemorySize, SMEM_BYTES);
    cudaFuncSetAttribute(gemm_qkv,   cudaFuncAttributeMaxDynamicSharedMemorySize, SMEM_BYTES);

    int gy = (Nn + TBM - 1) / TBM;

    init_kernel<<<(Nn + 255) / 256, 256>>>(Nn);
    ln_kernel<<<(Nn * 32 + 255) / 256, 256>>>(x, g1, be1, xn, Nn);
    // fused QKV
    {
        dim3 grid(6, gy);
        gemm_qkv<<<grid, 256, SMEM_BYTES>>>(xn, Wq, bq, q, Wk, bk, k, Wv, bv, v, Nn);
    }
    ep_kernel<<<4096, 256>>>(ef, We, be, E);
    hist_kernel<<<(E + 255) / 256, 256>>>(dst, E);
    scan_kernel<<<1, 1024>>>(Nn, E);
    scatter_kernel<<<(E + 255) / 256, 256>>>(src, dst, E);
    scores_kernel<<<(E + 7) / 8, 256>>>(ew, E);
    node_kernel<<<Nn, 256>>>(Nn);
    attn_out_kernel<<<(E + 255) / 256, 256>>>(out_attn, E);
    // output projection + residual -> x1
    {
        dim3 grid(DMODEL / TBN, gy);
        gemm_tc<2><<<grid, 256, SMEM_BYTES>>>(agg, Wo, bo, x, alpha, x1, Nn, DMODEL, DMODEL);
    }
    ln_kernel<<<(Nn * 32 + 255) / 256, 256>>>(x1, g2, be2, xn2, Nn);
    // FF
    {
        dim3 grid((4 * DMODEL) / TBN, gy);
        gemm_tc<1><<<grid, 256, SMEM_BYTES>>>(xn2, W1, b1, nullptr, nullptr, ff, Nn, 4 * DMODEL, DMODEL);
    }
    {
        dim3 grid(DMODEL / TBN, gy);
        gemm_tc<2><<<grid, 256, SMEM_BYTES>>>(ff, W2, b2, x1, beta, out_x, Nn, DMODEL, 4 * DMODEL);
    }
}

// round 8
// speedup vs baseline: 2.7425x; 1.0540x over previous
#include <cuda_runtime.h>
#include <cuda_bf16.h>
#include <math.h>

#define NMAX 50000
#define EMAX 1600000
#define DMODEL 256
#define NHEAD 8
#define HD 32

// ---------------- scratch (static device globals; no allocation) -------------
__device__ float g_xn  [(size_t)NMAX * DMODEL];
__device__ float g_q   [(size_t)NMAX * DMODEL];
__device__ float g_k   [(size_t)NMAX * DMODEL];
__device__ float g_v   [(size_t)NMAX * DMODEL];
__device__ float g_qw  [(size_t)NMAX * DMODEL];  // We^T q per head
__device__ float g_qbe [(size_t)NMAX * NHEAD];   // q . be per head
__device__ float g_sc  [(size_t)NHEAD * EMAX];   // [head][slot] transposed
__device__ float g_agg [(size_t)NMAX * DMODEL];
__device__ float g_x1  [(size_t)NMAX * DMODEL];
__device__ float g_xn2 [(size_t)NMAX * DMODEL];
__device__ float g_ff  [(size_t)NMAX * 4 * DMODEL];
// CSR build
__device__ int g_cnt   [NMAX];
__device__ int g_cur   [NMAX];
__device__ int g_rowptr[NMAX + 1];
__device__ int g_perm  [EMAX];
__device__ int g_src_s [EMAX];
__device__ int g_dst_s [EMAX];

__device__ __forceinline__ unsigned smem_u32(const void* p) {
    return (unsigned)__cvta_generic_to_shared(p);
}
__device__ __forceinline__ void cp_async16(unsigned daddr, const void* gptr, int szbytes) {
    asm volatile("cp.async.cg.shared.global [%0], [%1], 16, %2;\n"
                 :: "r"(daddr), "l"(gptr), "r"(szbytes));
}

// ---------------- init: zero CSR counters -----------------------------------
__global__ __launch_bounds__(256) void init_kernel(int Nn) {
    int i = blockIdx.x * 256 + threadIdx.x;
    if (i < Nn) { g_cnt[i] = 0; g_cur[i] = 0; }
}

// ---------------- LayerNorm: one warp per node ------------------------------
__global__ __launch_bounds__(256) void ln_kernel(const float* __restrict__ x,
                                                 const float* __restrict__ g,
                                                 const float* __restrict__ b,
                                                 float* __restrict__ out, int Nn) {
    int warp = (blockIdx.x * 256 + threadIdx.x) >> 5;
    int lane = threadIdx.x & 31;
    if (warp >= Nn) return;
    const float4* xr = (const float4*)(x + (size_t)warp * DMODEL);
    float4 a = xr[lane];
    float4 c = xr[lane + 32];
    float s = a.x + a.y + a.z + a.w + c.x + c.y + c.z + c.w;
    float q = a.x*a.x + a.y*a.y + a.z*a.z + a.w*a.w
            + c.x*c.x + c.y*c.y + c.z*c.z + c.w*c.w;
    #pragma unroll
    for (int o = 16; o; o >>= 1) {
        s += __shfl_xor_sync(0xFFFFFFFFu, s, o);
        q += __shfl_xor_sync(0xFFFFFFFFu, q, o);
    }
    float mu = s * (1.f / 256.f);
    float var = q * (1.f / 256.f) - mu * mu;
    float inv = rsqrtf(var + 1e-5f);
    float4 g0 = ((const float4*)g)[lane], g1 = ((const float4*)g)[lane + 32];
    float4 b0 = ((const float4*)b)[lane], b1 = ((const float4*)b)[lane + 32];
    float4 o0, o1;
    o0.x = (a.x - mu) * inv * g0.x + b0.x;
    o0.y = (a.y - mu) * inv * g0.y + b0.y;
    o0.z = (a.z - mu) * inv * g0.z + b0.z;
    o0.w = (a.w - mu) * inv * g0.w + b0.w;
    o1.x = (c.x - mu) * inv * g1.x + b1.x;
    o1.y = (c.y - mu) * inv * g1.y + b1.y;
    o1.z = (c.z - mu) * inv * g1.z + b1.z;
    o1.w = (c.w - mu) * inv * g1.w + b1.w;
    float4* orow = (float4*)(out + (size_t)warp * DMODEL);
    orow[lane] = o0;
    orow[lane + 32] = o1;
}

// ---------------- tf32 TC GEMM core: C = epi(A @ W^T + bias) ----------------
#define TBM 128
#define TBN 128
#define TBK 32
#define SSTR 36
#define BUFW ((TBM + TBN) * SSTR)
#define SMEM_BYTES (3 * BUFW * 4)

__device__ __forceinline__ void mma_tf32(float c[4], const unsigned a[4], const unsigned b[2]) {
    asm volatile(
        "mma.sync.aligned.m16n8k8.row.col.f32.tf32.tf32.f32 "
        "{%0,%1,%2,%3},{%4,%5,%6,%7},{%8,%9},{%0,%1,%2,%3};\n"
        : "+f"(c[0]), "+f"(c[1]), "+f"(c[2]), "+f"(c[3])
        : "r"(a[0]), "r"(a[1]), "r"(a[2]), "r"(a[3]), "r"(b[0]), "r"(b[1]));
}

template <int EPI>
__device__ __forceinline__ void gemm_core(
    const float* __restrict__ A, const float* __restrict__ W,
    const float* __restrict__ bias, const float* __restrict__ R,
    const float* __restrict__ scl, float* __restrict__ C,
    int M, int N, int K, int m0, int n0) {
    extern __shared__ unsigned smem[];
    const unsigned sBase = smem_u32(smem);
    const int tid = threadIdx.x;
    const int warp = tid >> 5, lane = tid & 31;
    const int wm = warp & 3, wn = warp >> 2;
    const int g = lane >> 2, t = lane & 3;

    float acc[2][8][4];
    #pragma unroll
    for (int mi = 0; mi < 2; mi++)
        #pragma unroll
        for (int ni = 0; ni < 8; ni++)
            #pragma unroll
            for (int j = 0; j < 4; j++) acc[mi][ni][j] = 0.f;

    auto stage = [&](int buf, int k0) {
        unsigned base = sBase + (unsigned)(buf * BUFW) * 4;
        #pragma unroll
        for (int i = 0; i < 4; i++) {
            int ch = tid + i * 256;
            int r = ch >> 3, c4 = (ch & 7) * 4;
            int m = m0 + r;
            int ok = (m < M);
            const float* gp = A + (size_t)(ok ? m : 0) * K + k0 + c4;
            cp_async16(base + (unsigned)(r * SSTR + c4) * 4, gp, ok ? 16 : 0);
        }
        #pragma unroll
        for (int i = 0; i < 4; i++) {
            int ch = tid + i * 256;
            int r = ch >> 3, c4 = (ch & 7) * 4;
            const float* gp = W + (size_t)(n0 + r) * K + k0 + c4;
            cp_async16(base + (unsigned)(TBM * SSTR + r * SSTR + c4) * 4, gp, 16);
        }
        asm volatile("cp.async.commit_group;\n");
    };

    auto compute = [&](int buf) {
        const unsigned* Ab = smem + buf * BUFW;
        const unsigned* Bb = Ab + TBM * SSTR;
        #pragma unroll
        for (int ks = 0; ks < 4; ks++) {
            int k = ks * 8;
            unsigned af[2][4], bf[8][2];
            #pragma unroll
            for (int mi = 0; mi < 2; mi++) {
                int r = wm * 32 + mi * 16;
                af[mi][0] = Ab[(r + g) * SSTR + k + t];
                af[mi][1] = Ab[(r + g + 8) * SSTR + k + t];
                af[mi][2] = Ab[(r + g) * SSTR + k + t + 4];
                af[mi][3] = Ab[(r + g + 8) * SSTR + k + t + 4];
            }
            #pragma unroll
            for (int ni = 0; ni < 8; ni++) {
                int c = wn * 64 + ni * 8 + g;
                bf[ni][0] = Bb[c * SSTR + k + t];
                bf[ni][1] = Bb[c * SSTR + k + t + 4];
            }
            #pragma unroll
            for (int mi = 0; mi < 2; mi++)
                #pragma unroll
                for (int ni = 0; ni < 8; ni++)
                    mma_tf32(acc[mi][ni], af[mi], bf[ni]);
        }
    };

    const int nk = K / TBK;
    stage(0, 0);
    stage(1, TBK);
    int buf = 0;
    for (int kt = 0; kt < nk; kt++) {
        if (kt + 1 < nk) asm volatile("cp.async.wait_group 1;\n");
        else             asm volatile("cp.async.wait_group 0;\n");
        __syncthreads();
        if (kt + 2 < nk) {
            int nb = buf + 2; if (nb >= 3) nb -= 3;
            stage(nb, (kt + 2) * TBK);
        }
        compute(buf);
        if (++buf == 3) buf = 0;
    }

    float al = (EPI == 2) ? scl[0] : 0.f;
    #pragma unroll
    for (int mi = 0; mi < 2; mi++) {
        #pragma unroll
        for (int ni = 0; ni < 8; ni++) {
            int col = n0 + wn * 64 + ni * 8 + 2 * t;
            float bx = bias[col], by = bias[col + 1];
            #pragma unroll
            for (int h = 0; h < 2; h++) {
                int row = m0 + wm * 32 + mi * 16 + g + h * 8;
                if (row >= M) continue;
                float v0 = acc[mi][ni][h * 2 + 0] + bx;
                float v1 = acc[mi][ni][h * 2 + 1] + by;
                if (EPI == 1) {
                    v0 = 0.5f * v0 * (1.f + erff(v0 * 0.70710678118654752f));
                    v1 = 0.5f * v1 * (1.f + erff(v1 * 0.70710678118654752f));
                }
                if (EPI == 2) {
                    const float* rr = R + (size_t)row * N + col;
                    v0 = rr[0] + al * v0;
                    v1 = rr[1] + al * v1;
                }
                *(float2*)(C + (size_t)row * N + col) = make_float2(v0, v1);
            }
        }
    }
}

template <int EPI>
__global__ __launch_bounds__(256, 2) void gemm_tc(
    const float* __restrict__ A, const float* __restrict__ W,
    const float* __restrict__ bias, const float* __restrict__ R,
    const float* __restrict__ scl, float* __restrict__ C,
    int M, int N, int K) {
    gemm_core<EPI>(A, W, bias, R, scl, C, M, N, K,
                   blockIdx.y * TBM, blockIdx.x * TBN);
}

__global__ __launch_bounds__(256, 2) void gemm_qkv(
    const float* __restrict__ A,
    const float* __restrict__ Wq, const float* __restrict__ bq, float* __restrict__ q,
    const float* __restrict__ Wk, const float* __restrict__ bk, float* __restrict__ k,
    const float* __restrict__ Wv, const float* __restrict__ bv, float* __restrict__ v,
    int M) {
    int sel = blockIdx.x >> 1;
    int n0 = (blockIdx.x & 1) * TBN;
    const float* W = (sel == 0) ? Wq : (sel == 1) ? Wk : Wv;
    const float* b = (sel == 0) ? bq : (sel == 1) ? bk : bv;
    float* C       = (sel == 0) ? q  : (sel == 1) ? k  : v;
    gemm_core<0>(A, W, b, nullptr, nullptr, C, M, DMODEL, DMODEL,
                 blockIdx.y * TBM, n0);
}

// ---------------- qW = We^T q per head; qbe = q.be per head ------------------
// Warp per node. ep is folded into scores via linearity:
//   q.(k + We ef + be) = q.k + (We^T q).ef + q.be
__global__ __launch_bounds__(256) void qw_kernel(const float* __restrict__ We,
                                                 const float* __restrict__ be,
                                                 int Nn) {
    __shared__ float sWe[32 * 32];  // raw We[j*32+i]
    int tid = threadIdx.x;
    for (int t = tid; t < 1024; t += 256) sWe[t] = We[t];
    __syncthreads();
    int node = (blockIdx.x * 256 + tid) >> 5;
    int lane = tid & 31;
    if (node >= Nn) return;
    float wreg[32];
    #pragma unroll
    for (int j = 0; j < 32; j++) wreg[j] = sWe[j * 32 + lane];  // We[j][lane], conflict-free
    float ber = be[lane];
    const float* qrow = g_q + (size_t)node * DMODEL;
    float* qwrow = g_qw + (size_t)node * DMODEL;
    #pragma unroll
    for (int h = 0; h < NHEAD; h++) {
        float qv = qrow[h * 32 + lane];
        // qbe
        float pb = qv * ber;
        #pragma unroll
        for (int o = 16; o; o >>= 1) pb += __shfl_xor_sync(0xFFFFFFFFu, pb, o);
        if (lane == 0) g_qbe[(size_t)node * NHEAD + h] = pb;
        // qW[i] = sum_j q_j * We[j][i]
        float acc = 0.f;
        #pragma unroll
        for (int j = 0; j < 32; j++)
            acc += __shfl_sync(0xFFFFFFFFu, qv, j) * wreg[j];
        qwrow[h * 32 + lane] = acc;
    }
}

// ---------------- CSR build --------------------------------------------------
__global__ __launch_bounds__(256) void hist_kernel(const int* __restrict__ dst, int E) {
    int i = blockIdx.x * 256 + threadIdx.x;
    if (i < E) atomicAdd(&g_cnt[dst[i]], 1);
}

__global__ __launch_bounds__(1024) void scan_kernel(int Nn, int E) {
    const int tid = threadIdx.x;
    const int lane = tid & 31, wid = tid >> 5;
    __shared__ int warp_sums[32];
    __shared__ int carry;
    if (tid == 0) carry = 0;
    __syncthreads();
    for (int base = 0; base < Nn; base += 1024) {
        int i = base + tid;
        int v = (i < Nn) ? g_cnt[i] : 0;
        int x = v;
        #pragma unroll
        for (int o = 1; o < 32; o <<= 1) {
            int y = __shfl_up_sync(0xFFFFFFFFu, x, o);
            if (lane >= o) x += y;
        }
        if (lane == 31) warp_sums[wid] = x;
        __syncthreads();
        if (wid == 0) {
            int s = warp_sums[lane];
            #pragma unroll
            for (int o = 1; o < 32; o <<= 1) {
                int y = __shfl_up_sync(0xFFFFFFFFu, s, o);
                if (lane >= o) s += y;
            }
            warp_sums[lane] = s;
        }
        __syncthreads();
        int offset = carry + (wid ? warp_sums[wid - 1] : 0);
        if (i < Nn) g_rowptr[i] = offset + x - v;
        int blocktotal = warp_sums[31];
        __syncthreads();
        if (tid == 0) carry += blocktotal;
        __syncthreads();
    }
    if (tid == 0) g_rowptr[Nn] = E;
}

__global__ __launch_bounds__(256) void scatter_kernel(const int* __restrict__ src,
                                                      const int* __restrict__ dst, int E) {
    int i = blockIdx.x * 256 + threadIdx.x;
    if (i >= E) return;
    int d = dst[i];
    int slot = g_rowptr[d] + atomicAdd(&g_cur[d], 1);
    g_perm[slot] = i;
    g_src_s[slot] = src[i];
    g_dst_s[slot] = d;
}

// ---------------- scores: warp per slot; ep folded in ------------------------
__global__ __launch_bounds__(256) void scores_kernel(const float* __restrict__ ef,
                                                     const float* __restrict__ ew, int E) {
    __shared__ float sSc[NHEAD][8];
    int warp = threadIdx.x >> 5;
    int lane = threadIdx.x & 31;
    int slot = blockIdx.x * 8 + warp;
    if (slot < E) {
        int pe = g_perm[slot];
        int d = g_dst_s[slot];
        int s = g_src_s[slot];
        int h = lane >> 2, part = lane & 3;
        const float4* q4 = (const float4*)(g_q + (size_t)d * DMODEL + h * 32 + part * 8);
        const float4* k4 = (const float4*)(g_k + (size_t)s * DMODEL + h * 32 + part * 8);
        const float4* w4 = (const float4*)(g_qw + (size_t)d * DMODEL + h * 32 + part * 8);
        const float4* e4 = (const float4*)(ef + (size_t)pe * 32 + part * 8);
        float4 qa = q4[0], qb = q4[1];
        float4 ka = k4[0], kb = k4[1];
        float4 wa = w4[0], wb = w4[1];
        float4 ea = e4[0], eb = e4[1];
        float p = qa.x * ka.x + qa.y * ka.y + qa.z * ka.z + qa.w * ka.w
                + qb.x * kb.x + qb.y * kb.y + qb.z * kb.z + qb.w * kb.w
                + wa.x * ea.x + wa.y * ea.y + wa.z * ea.z + wa.w * ea.w
                + wb.x * eb.x + wb.y * eb.y + wb.z * eb.z + wb.w * eb.w;
        p += __shfl_xor_sync(0xFFFFFFFFu, p, 1);
        p += __shfl_xor_sync(0xFFFFFFFFu, p, 2);
        if (part == 0) {
            p += g_qbe[(size_t)d * NHEAD + h];
            sSc[h][warp] = p * ew[pe] * 0.17677669529663687f;
        }
    }
    __syncthreads();
    if (threadIdx.x < 64) {
        int h = threadIdx.x >> 3, i = threadIdx.x & 7;
        int si = blockIdx.x * 8 + i;
        if (si < E) g_sc[(size_t)h * EMAX + si] = sSc[h][i];
    }
}

// ---------------- per-node softmax + aggregate (no atomics) ------------------
__global__ __launch_bounds__(256) void node_kernel(int Nn) {
    int d = blockIdx.x;
    if (d >= Nn) return;
    int h = threadIdx.x >> 5, lane = threadIdx.x & 31;
    int b0 = g_rowptr[d], b1 = g_rowptr[d + 1];
    float* schead = g_sc + (size_t)h * EMAX;

    float m = -1e30f;
    for (int s = b0 + lane; s < b1; s += 32)
        m = fmaxf(m, schead[s]);
    #pragma unroll
    for (int o = 16; o; o >>= 1) m = fmaxf(m, __shfl_xor_sync(0xFFFFFFFFu, m, o));

    float sum = 0.f;
    for (int s = b0 + lane; s < b1; s += 32) {
        float w = __expf(schead[s] - m);
        schead[s] = w;
        sum += w;
    }
    #pragma unroll
    for (int o = 16; o; o >>= 1) sum += __shfl_xor_sync(0xFFFFFFFFu, sum, o);
    float inv = 1.f / sum;

    float a0 = 0.f, a1 = 0.f, a2 = 0.f, a3 = 0.f;
    const float* vbase = g_v + h * 32 + lane;
    for (int s0 = b0; s0 < b1; s0 += 32) {
        int n = min(32, b1 - s0);
        float w = 0.f; int sn = 0;
        if (lane < n) {
            w = schead[s0 + lane] * inv;
            sn = g_src_s[s0 + lane];
            schead[s0 + lane] = w;
        }
        int j = 0;
        for (; j + 8 <= n; j += 8) {
            float w0 = __shfl_sync(0xFFFFFFFFu, w, j + 0);
            float w1 = __shfl_sync(0xFFFFFFFFu, w, j + 1);
            float w2 = __shfl_sync(0xFFFFFFFFu, w, j + 2);
            float w3 = __shfl_sync(0xFFFFFFFFu, w, j + 3);
            float w4 = __shfl_sync(0xFFFFFFFFu, w, j + 4);
            float w5 = __shfl_sync(0xFFFFFFFFu, w, j + 5);
            float w6 = __shfl_sync(0xFFFFFFFFu, w, j + 6);
            float w7 = __shfl_sync(0xFFFFFFFFu, w, j + 7);
            int i0 = __shfl_sync(0xFFFFFFFFu, sn, j + 0);
            int i1 = __shfl_sync(0xFFFFFFFFu, sn, j + 1);
            int i2 = __shfl_sync(0xFFFFFFFFu, sn, j + 2);
            int i3 = __shfl_sync(0xFFFFFFFFu, sn, j + 3);
            int i4 = __shfl_sync(0xFFFFFFFFu, sn, j + 4);
            int i5 = __shfl_sync(0xFFFFFFFFu, sn, j + 5);
            int i6 = __shfl_sync(0xFFFFFFFFu, sn, j + 6);
            int i7 = __shfl_sync(0xFFFFFFFFu, sn, j + 7);
            a0 += w0 * vbase[(size_t)i0 * DMODEL];
            a1 += w1 * vbase[(size_t)i1 * DMODEL];
            a2 += w2 * vbase[(size_t)i2 * DMODEL];
            a3 += w3 * vbase[(size_t)i3 * DMODEL];
            a0 += w4 * vbase[(size_t)i4 * DMODEL];
            a1 += w5 * vbase[(size_t)i5 * DMODEL];
            a2 += w6 * vbase[(size_t)i6 * DMODEL];
            a3 += w7 * vbase[(size_t)i7 * DMODEL];
        }
        for (; j < n; j++) {
            float wj = __shfl_sync(0xFFFFFFFFu, w, j);
            int ij = __shfl_sync(0xFFFFFFFFu, sn, j);
            a0 += wj * vbase[(size_t)ij * DMODEL];
        }
    }
    g_agg[(size_t)d * DMODEL + h * 32 + lane] = (a0 + a1) + (a2 + a3);
}

// ---------------- permute attn weights to original edge order ----------------
__global__ __launch_bounds__(256) void attn_out_kernel(float* __restrict__ out_attn, int E) {
    int e = blockIdx.x * 256 + threadIdx.x;
    if (e >= E) return;
    int orig = g_perm[e];
    float4 w0, w1;
    w0.x = g_sc[(size_t)0 * EMAX + e];
    w0.y = g_sc[(size_t)1 * EMAX + e];
    w0.z = g_sc[(size_t)2 * EMAX + e];
    w0.w = g_sc[(size_t)3 * EMAX + e];
    w1.x = g_sc[(size_t)4 * EMAX + e];
    w1.y = g_sc[(size_t)5 * EMAX + e];
    w1.z = g_sc[(size_t)6 * EMAX + e];
    w1.w = g_sc[(size_t)7 * EMAX + e];
    float4* op = (float4*)(out_attn + (size_t)orig * NHEAD);
    op[0] = w0;
    op[1] = w1;
}

// ---------------- host launcher ---------------------------------------------
static float* sym_addr(const void* symbol) {
    void* p = nullptr;
    cudaGetSymbolAddress(&p, symbol);
    return (float*)p;
}

extern "C" void kernel_launch(void* const* d_in, const int* in_sizes, int n_in,
                              void* d_out, int out_size) {
    const float* x  = (const float*)d_in[0];
    const int*   ei = (const int*)d_in[1];
    const float* ef = (const float*)d_in[2];
    const float* ew = (const float*)d_in[3];
    const float* Wq = (const float*)d_in[4];
    const float* bq = (const float*)d_in[5];
    const float* Wk = (const float*)d_in[6];
    const float* bk = (const float*)d_in[7];
    const float* Wv = (const float*)d_in[8];
    const float* bv = (const float*)d_in[9];
    const float* We = (const float*)d_in[10];
    const float* be = (const float*)d_in[11];
    const float* Wo = (const float*)d_in[12];
    const float* bo = (const float*)d_in[13];
    const float* W1 = (const float*)d_in[14];
    const float* b1 = (const float*)d_in[15];
    const float* W2 = (const float*)d_in[16];
    const float* b2 = (const float*)d_in[17];
    const float* g1 = (const float*)d_in[18];
    const float* be1 = (const float*)d_in[19];
    const float* g2 = (const float*)d_in[20];
    const float* be2 = (const float*)d_in[21];
    const float* alpha = (const float*)d_in[22];
    const float* beta  = (const float*)d_in[23];

    int Nn = in_sizes[0] / DMODEL;
    int E  = in_sizes[1] / 2;
    const int* src = ei;
    const int* dst = ei + E;

    float* out_x    = (float*)d_out;
    float* out_attn = out_x + (size_t)Nn * DMODEL;

    float* xn  = sym_addr(g_xn);
    float* q   = sym_addr(g_q);
    float* k   = sym_addr(g_k);
    float* v   = sym_addr(g_v);
    float* agg = sym_addr(g_agg);
    float* x1  = sym_addr(g_x1);
    float* xn2 = sym_addr(g_xn2);
    float* ff  = sym_addr(g_ff);

    cudaFuncSetAttribute(gemm_tc<0>, cudaFuncAttributeMaxDynamicSharedMemorySize, SMEM_BYTES);
    cudaFuncSetAttribute(gemm_tc<1>, cudaFuncAttributeMaxDynamicSharedMemorySize, SMEM_BYTES);
    cudaFuncSetAttribute(gemm_tc<2>, cudaFuncAttributeMaxDynamicSharedMemorySize, SMEM_BYTES);
    cudaFuncSetAttribute(gemm_qkv,   cudaFuncAttributeMaxDynamicSharedMemorySize, SMEM_BYTES);

    int gy = (Nn + TBM - 1) / TBM;

    init_kernel<<<(Nn + 255) / 256, 256>>>(Nn);
    ln_kernel<<<(Nn * 32 + 255) / 256, 256>>>(x, g1, be1, xn, Nn);
    {
        dim3 grid(6, gy);
        gemm_qkv<<<grid, 256, SMEM_BYTES>>>(xn, Wq, bq, q, Wk, bk, k, Wv, bv, v, Nn);
    }
    qw_kernel<<<(Nn * 32 + 255) / 256, 256>>>(We, be, Nn);
    hist_kernel<<<(E + 255) / 256, 256>>>(dst, E);
    scan_kernel<<<1, 1024>>>(Nn, E);
    scatter_kernel<<<(E + 255) / 256, 256>>>(src, dst, E);
    scores_kernel<<<(E + 7) / 8, 256>>>(ef, ew, E);
    node_kernel<<<Nn, 256>>>(Nn);
    attn_out_kernel<<<(E + 255) / 256, 256>>>(out_attn, E);
    {
        dim3 grid(DMODEL / TBN, gy);
        gemm_tc<2><<<grid, 256, SMEM_BYTES>>>(agg, Wo, bo, x, alpha, x1, Nn, DMODEL, DMODEL);
    }
    ln_kernel<<<(Nn * 32 + 255) / 256, 256>>>(x1, g2, be2, xn2, Nn);
    {
        dim3 grid((4 * DMODEL) / TBN, gy);
        gemm_tc<1><<<grid, 256, SMEM_BYTES>>>(xn2, W1, b1, nullptr, nullptr, ff, Nn, 4 * DMODEL, DMODEL);
    }
    {
        dim3 grid(DMODEL / TBN, gy);
        gemm_tc<2><<<grid, 256, SMEM_BYTES>>>(ff, W2, b2, x1, beta, out_x, Nn, DMODEL, 4 * DMODEL);
    }
}